// round 1
// baseline (speedup 1.0000x reference)
#include <cuda_runtime.h>
#include <math.h>

#define NTOK 65536
#define DIM 256
#define HID 1024
#define NE 8
#define MAXTILES 519   // sum_e ceil(cnt_e/128) <= 512 + 7

// ---------------- device scratch (static globals: allowed) ----------------
__device__ float g_xavg[16 * 256];
__device__ float g_avglogit[16 * NE];
__device__ int   g_cnt[NE];
__device__ int   g_tileBase[NE + 1];
__device__ int   g_tok[NE * NTOK];
__device__ float g_gate[NTOK];
__device__ float g_hidden[(size_t)MAXTILES * 128 * HID];  // ~272 MB, zero-init

// ---------------- K1: adaptive avg pool over (H,W) ----------------
__global__ void avgpool_kernel(const float* __restrict__ x) {
    int c = blockIdx.x, b = blockIdx.y;
    const float4* p = (const float4*)(x + ((size_t)b * DIM + c) * 4096);
    int tid = threadIdx.x;
    float s = 0.f;
#pragma unroll
    for (int j = 0; j < 4; j++) {
        float4 v = p[tid + 256 * j];
        s += v.x + v.y + v.z + v.w;
    }
#pragma unroll
    for (int o = 16; o > 0; o >>= 1) s += __shfl_xor_sync(0xFFFFFFFFu, s, o);
    __shared__ float ws[8];
    if ((tid & 31) == 0) ws[tid >> 5] = s;
    __syncthreads();
    if (tid == 0) {
        float t = 0.f;
#pragma unroll
        for (int i = 0; i < 8; i++) t += ws[i];
        g_xavg[b * 256 + c] = t * (1.0f / 4096.0f);
    }
}

// ---------------- K2: avg logits + zero counters ----------------
__global__ void prep_kernel(const float* __restrict__ Wa, const float* __restrict__ ba) {
    int t = threadIdx.x;
    if (t < NE) g_cnt[t] = 0;
    if (t < 128) {
        int b = t >> 3, e = t & 7;
        float acc = 0.f;
        for (int c = 0; c < 256; c++) acc += g_xavg[b * 256 + c] * Wa[c * 8 + e];
        g_avglogit[t] = acc + ba[e];
    }
}

// ---------------- K3: router (per token: logits, noise, top-2, gate) ----------------
__global__ void router_kernel(const float* __restrict__ x, const float* __restrict__ noise,
                              const float* __restrict__ Wr, const float* __restrict__ br,
                              const float* __restrict__ Wn, const float* __restrict__ bn) {
    __shared__ float sWr[2048], sWn[2048];
    __shared__ float sbr[8], sbn[8], sAvg[8];
    __shared__ int scnt[8], sbase[8];
    int tid = threadIdx.x;
    int i = blockIdx.x * 256 + tid;
    int b = i >> 12;  // 4096 tokens per batch; whole block is same batch
    for (int j = tid; j < 2048; j += 256) { sWr[j] = Wr[j]; sWn[j] = Wn[j]; }
    if (tid < 8) {
        sbr[tid] = br[tid]; sbn[tid] = bn[tid];
        sAvg[tid] = g_avglogit[b * 8 + tid];
        scnt[tid] = 0;
    }
    __syncthreads();

    float ar[8] = {0, 0, 0, 0, 0, 0, 0, 0};
    float an[8] = {0, 0, 0, 0, 0, 0, 0, 0};
    const float4* xp = (const float4*)(x + (size_t)i * DIM);

#define ROUT_STEP(xc, kk)                                                            \
    {                                                                                \
        float4 w0 = *(const float4*)&sWr[(kk) * 8];                                  \
        float4 w1 = *(const float4*)&sWr[(kk) * 8 + 4];                              \
        float4 u0 = *(const float4*)&sWn[(kk) * 8];                                  \
        float4 u1 = *(const float4*)&sWn[(kk) * 8 + 4];                              \
        ar[0] += (xc) * w0.x; ar[1] += (xc) * w0.y; ar[2] += (xc) * w0.z;            \
        ar[3] += (xc) * w0.w; ar[4] += (xc) * w1.x; ar[5] += (xc) * w1.y;            \
        ar[6] += (xc) * w1.z; ar[7] += (xc) * w1.w;                                  \
        an[0] += (xc) * u0.x; an[1] += (xc) * u0.y; an[2] += (xc) * u0.z;            \
        an[3] += (xc) * u0.w; an[4] += (xc) * u1.x; an[5] += (xc) * u1.y;            \
        an[6] += (xc) * u1.z; an[7] += (xc) * u1.w;                                  \
    }

#pragma unroll 4
    for (int k4 = 0; k4 < 64; k4++) {
        float4 xv = xp[k4];
        int k = k4 * 4;
        ROUT_STEP(xv.x, k + 0);
        ROUT_STEP(xv.y, k + 1);
        ROUT_STEP(xv.z, k + 2);
        ROUT_STEP(xv.w, k + 3);
    }
#undef ROUT_STEP

    float noisy[8];
    const float* np = noise + (size_t)i * 8;
#pragma unroll
    for (int e = 0; e < 8; e++) {
        float lg = ar[e] + sbr[e] + sAvg[e];
        float z = an[e] + sbn[e];
        float sp = fmaxf(z, 0.f) + log1pf(expf(-fabsf(z)));  // softplus, stable
        noisy[e] = lg + np[e] * sp;
    }
    // top-2 (first-occurrence tie-break, matching lax.top_k)
    int i1 = 0; float v1 = noisy[0];
#pragma unroll
    for (int e = 1; e < 8; e++) if (noisy[e] > v1) { v1 = noisy[e]; i1 = e; }
    int i2 = -1; float v2 = -INFINITY;
#pragma unroll
    for (int e = 0; e < 8; e++) if (e != i1 && noisy[e] > v2) { v2 = noisy[e]; i2 = e; }

    // softmax over [v1, v2] (v1 >= v2); surviving expert = larger INDEX (overwrite semantics)
    float t = expf(v2 - v1);
    float s1 = 1.f / (1.f + t);
    int es; float g;
    if (i1 > i2) { es = i1; g = s1; }
    else         { es = i2; g = t / (1.f + t); }

    int pl = atomicAdd(&scnt[es], 1);
    __syncthreads();
    if (tid < 8) sbase[tid] = atomicAdd(&g_cnt[tid], scnt[tid]);
    __syncthreads();
    g_tok[es * NTOK + sbase[es] + pl] = i;
    g_gate[i] = g;
}

// ---------------- K4: per-expert tile offsets ----------------
__global__ void scan_kernel() {
    if (threadIdx.x == 0) {
        int tb = 0;
        for (int e = 0; e < NE; e++) {
            g_tileBase[e] = tb;
            tb += (g_cnt[e] + 127) >> 7;
        }
        g_tileBase[NE] = tb;
    }
}

// ---------------- grouped SGEMM helpers ----------------
// 128x128 tile, 256 threads, 8x8 micro-tile, K-chunk 16, transposed A staging.

__global__ void __launch_bounds__(256, 2)
gemmA_kernel(const float* __restrict__ x, const float* __restrict__ W1,
             const float* __restrict__ b1) {
    __shared__ float Ast[16][128];
    __shared__ float Bs[16][128];
    __shared__ int rowTok[128];
    __shared__ int sMeta[3];  // e, tokbase, rem
    const int tid = threadIdx.x;

    if (tid == 0) {
        int bx = blockIdx.x;
        int e = -1, rem = 0, tokbase = 0;
        if (bx < g_tileBase[NE]) {
            e = 0;
            while (bx >= g_tileBase[e + 1]) e++;
            int lt = bx - g_tileBase[e];
            tokbase = e * NTOK + lt * 128;
            rem = g_cnt[e] - lt * 128;
        }
        sMeta[0] = e; sMeta[1] = tokbase; sMeta[2] = rem;
    }
    __syncthreads();
    const int e = sMeta[0];
    if (e < 0) return;
    const int rem = sMeta[2];
    if (tid < 128) rowTok[tid] = (tid < rem) ? g_tok[sMeta[1] + tid] : -1;
    __syncthreads();

    const int tx = tid & 15, ty = tid >> 4;
    const int n0 = blockIdx.y * 128;
    const float* Wp = W1 + (size_t)e * DIM * HID + n0;
    const int mL = tid & 127, kb = (tid >> 7) << 3;
    const int kB = tid >> 4, nb = (tid & 15) << 3;
    const int trL = rowTok[mL];
    const float* aPtr = x + (size_t)(trL < 0 ? 0 : trL) * DIM + kb;

    float acc[8][8];
#pragma unroll
    for (int i = 0; i < 8; i++)
#pragma unroll
        for (int j = 0; j < 8; j++) acc[i][j] = 0.f;

    for (int kt = 0; kt < DIM; kt += 16) {
        float4 a0 = make_float4(0, 0, 0, 0), a1 = make_float4(0, 0, 0, 0);
        if (trL >= 0) {
            a0 = *(const float4*)(aPtr + kt);
            a1 = *(const float4*)(aPtr + kt + 4);
        }
        const float* bp = Wp + (size_t)(kt + kB) * HID + nb;
        float4 b0 = *(const float4*)bp;
        float4 b1v = *(const float4*)(bp + 4);
        __syncthreads();
        Ast[kb + 0][mL] = a0.x; Ast[kb + 1][mL] = a0.y;
        Ast[kb + 2][mL] = a0.z; Ast[kb + 3][mL] = a0.w;
        Ast[kb + 4][mL] = a1.x; Ast[kb + 5][mL] = a1.y;
        Ast[kb + 6][mL] = a1.z; Ast[kb + 7][mL] = a1.w;
        *(float4*)&Bs[kB][nb] = b0;
        *(float4*)&Bs[kB][nb + 4] = b1v;
        __syncthreads();
#pragma unroll
        for (int k = 0; k < 16; k++) {
            float4 pa0 = *(const float4*)&Ast[k][ty * 8];
            float4 pa1 = *(const float4*)&Ast[k][ty * 8 + 4];
            float4 pb0 = *(const float4*)&Bs[k][tx * 8];
            float4 pb1 = *(const float4*)&Bs[k][tx * 8 + 4];
            float av[8] = {pa0.x, pa0.y, pa0.z, pa0.w, pa1.x, pa1.y, pa1.z, pa1.w};
            float bv[8] = {pb0.x, pb0.y, pb0.z, pb0.w, pb1.x, pb1.y, pb1.z, pb1.w};
#pragma unroll
            for (int i = 0; i < 8; i++)
#pragma unroll
                for (int j = 0; j < 8; j++) acc[i][j] += av[i] * bv[j];
        }
    }

    float4 bb0 = *(const float4*)(b1 + (size_t)e * HID + n0 + tx * 8);
    float4 bb1 = *(const float4*)(b1 + (size_t)e * HID + n0 + tx * 8 + 4);
    float bias[8] = {bb0.x, bb0.y, bb0.z, bb0.w, bb1.x, bb1.y, bb1.z, bb1.w};
#pragma unroll
    for (int i = 0; i < 8; i++) {
        int m = ty * 8 + i;
        if (m < rem) {
            float* op = g_hidden + ((size_t)blockIdx.x * 128 + m) * HID + n0 + tx * 8;
            float4 o0, o1;
            o0.x = fmaxf(acc[i][0] + bias[0], 0.f);
            o0.y = fmaxf(acc[i][1] + bias[1], 0.f);
            o0.z = fmaxf(acc[i][2] + bias[2], 0.f);
            o0.w = fmaxf(acc[i][3] + bias[3], 0.f);
            o1.x = fmaxf(acc[i][4] + bias[4], 0.f);
            o1.y = fmaxf(acc[i][5] + bias[5], 0.f);
            o1.z = fmaxf(acc[i][6] + bias[6], 0.f);
            o1.w = fmaxf(acc[i][7] + bias[7], 0.f);
            *(float4*)op = o0;
            *(float4*)(op + 4) = o1;
        }
    }
}

__global__ void __launch_bounds__(256, 2)
gemmB_kernel(const float* __restrict__ W2, const float* __restrict__ b2,
             float* __restrict__ out) {
    __shared__ float Ast[16][128];
    __shared__ float Bs[16][128];
    __shared__ int rowTok[128];
    __shared__ int sMeta[3];
    const int tid = threadIdx.x;

    if (tid == 0) {
        int bx = blockIdx.x;
        int e = -1, rem = 0, tokbase = 0;
        if (bx < g_tileBase[NE]) {
            e = 0;
            while (bx >= g_tileBase[e + 1]) e++;
            int lt = bx - g_tileBase[e];
            tokbase = e * NTOK + lt * 128;
            rem = g_cnt[e] - lt * 128;
        }
        sMeta[0] = e; sMeta[1] = tokbase; sMeta[2] = rem;
    }
    __syncthreads();
    const int e = sMeta[0];
    if (e < 0) return;
    const int rem = sMeta[2];
    if (tid < 128) rowTok[tid] = (tid < rem) ? g_tok[sMeta[1] + tid] : -1;
    __syncthreads();

    const int tx = tid & 15, ty = tid >> 4;
    const int n0 = blockIdx.y * 128;
    const float* Wp = W2 + (size_t)e * HID * DIM + n0;
    const int mL = tid & 127, kb = (tid >> 7) << 3;
    const int kB = tid >> 4, nb = (tid & 15) << 3;
    const float* aPtr = g_hidden + ((size_t)blockIdx.x * 128 + mL) * HID + kb;

    float acc[8][8];
#pragma unroll
    for (int i = 0; i < 8; i++)
#pragma unroll
        for (int j = 0; j < 8; j++) acc[i][j] = 0.f;

    for (int kt = 0; kt < HID; kt += 16) {
        float4 a0 = *(const float4*)(aPtr + kt);
        float4 a1 = *(const float4*)(aPtr + kt + 4);
        const float* bp = Wp + (size_t)(kt + kB) * DIM + nb;
        float4 b0 = *(const float4*)bp;
        float4 b1v = *(const float4*)(bp + 4);
        __syncthreads();
        Ast[kb + 0][mL] = a0.x; Ast[kb + 1][mL] = a0.y;
        Ast[kb + 2][mL] = a0.z; Ast[kb + 3][mL] = a0.w;
        Ast[kb + 4][mL] = a1.x; Ast[kb + 5][mL] = a1.y;
        Ast[kb + 6][mL] = a1.z; Ast[kb + 7][mL] = a1.w;
        *(float4*)&Bs[kB][nb] = b0;
        *(float4*)&Bs[kB][nb + 4] = b1v;
        __syncthreads();
#pragma unroll
        for (int k = 0; k < 16; k++) {
            float4 pa0 = *(const float4*)&Ast[k][ty * 8];
            float4 pa1 = *(const float4*)&Ast[k][ty * 8 + 4];
            float4 pb0 = *(const float4*)&Bs[k][tx * 8];
            float4 pb1 = *(const float4*)&Bs[k][tx * 8 + 4];
            float av[8] = {pa0.x, pa0.y, pa0.z, pa0.w, pa1.x, pa1.y, pa1.z, pa1.w};
            float bv[8] = {pb0.x, pb0.y, pb0.z, pb0.w, pb1.x, pb1.y, pb1.z, pb1.w};
#pragma unroll
            for (int i = 0; i < 8; i++)
#pragma unroll
                for (int j = 0; j < 8; j++) acc[i][j] += av[i] * bv[j];
        }
    }

    float4 bb0 = *(const float4*)(b2 + (size_t)e * DIM + n0 + tx * 8);
    float4 bb1 = *(const float4*)(b2 + (size_t)e * DIM + n0 + tx * 8 + 4);
    float bias[8] = {bb0.x, bb0.y, bb0.z, bb0.w, bb1.x, bb1.y, bb1.z, bb1.w};
#pragma unroll
    for (int i = 0; i < 8; i++) {
        int m = ty * 8 + i;
        if (m < rem) {
            int tr = rowTok[m];
            float gte = g_gate[tr];
            float* op = out + (size_t)tr * DIM + n0 + tx * 8;
            float4 o0, o1;
            o0.x = (acc[i][0] + bias[0]) * gte;
            o0.y = (acc[i][1] + bias[1]) * gte;
            o0.z = (acc[i][2] + bias[2]) * gte;
            o0.w = (acc[i][3] + bias[3]) * gte;
            o1.x = (acc[i][4] + bias[4]) * gte;
            o1.y = (acc[i][5] + bias[5]) * gte;
            o1.z = (acc[i][6] + bias[6]) * gte;
            o1.w = (acc[i][7] + bias[7]) * gte;
            *(float4*)op = o0;
            *(float4*)(op + 4) = o1;
        }
    }
}

// ---------------- launch ----------------
extern "C" void kernel_launch(void* const* d_in, const int* in_sizes, int n_in,
                              void* d_out, int out_size) {
    const float* x     = (const float*)d_in[0];
    const float* noise = (const float*)d_in[1];
    const float* Wr    = (const float*)d_in[2];
    const float* br    = (const float*)d_in[3];
    const float* Wa    = (const float*)d_in[4];
    const float* ba    = (const float*)d_in[5];
    const float* Wn    = (const float*)d_in[6];
    const float* bn    = (const float*)d_in[7];
    const float* W1    = (const float*)d_in[8];
    const float* b1    = (const float*)d_in[9];
    const float* W2    = (const float*)d_in[10];
    const float* b2    = (const float*)d_in[11];
    float* out = (float*)d_out;

    avgpool_kernel<<<dim3(256, 16), 256>>>(x);
    prep_kernel<<<1, 128>>>(Wa, ba);
    router_kernel<<<256, 256>>>(x, noise, Wr, br, Wn, bn);
    scan_kernel<<<1, 1>>>();
    gemmA_kernel<<<dim3(MAXTILES, 8), 256>>>(x, W1, b1);
    gemmB_kernel<<<dim3(MAXTILES, 2), 256>>>(W2, b2, out);
}

// round 3
// speedup vs baseline: 2.3799x; 2.3799x over previous
#include <cuda_runtime.h>
#include <math.h>
#include <stdint.h>

#define NTOK 65536
#define DIM 256
#define HID 1024
#define NE 8
#define MAXTILES 519

// ---------------- device scratch ----------------
__device__ float g_xavg[16 * 256];
__device__ float g_avglogit[16 * NE];
__device__ int   g_cnt[NE];
__device__ int   g_tileBase[NE + 1];
__device__ int   g_tok[NE * NTOK];
__device__ float g_gate[NTOK];
// hidden per tile: [tile][m(128)][HID]
__device__ float g_hidden[(size_t)MAXTILES * 128 * HID];

// ---------------- helpers ----------------
__device__ __forceinline__ uint32_t f2tf(float f) {
    uint32_t u; asm("cvt.rna.tf32.f32 %0, %1;" : "=r"(u) : "f"(f)); return u;
}

__device__ __forceinline__ void mma_tf32(float* d, const uint32_t* a, const uint32_t* b) {
    asm volatile(
        "mma.sync.aligned.m16n8k8.row.col.f32.tf32.tf32.f32 "
        "{%0,%1,%2,%3}, {%4,%5,%6,%7}, {%8,%9}, {%0,%1,%2,%3};"
        : "+f"(d[0]), "+f"(d[1]), "+f"(d[2]), "+f"(d[3])
        : "r"(a[0]), "r"(a[1]), "r"(a[2]), "r"(a[3]), "r"(b[0]), "r"(b[1]));
}

// ---------------- K1: adaptive avg pool over (H,W) ----------------
__global__ void avgpool_kernel(const float* __restrict__ x) {
    int c = blockIdx.x, b = blockIdx.y;
    const float4* p = (const float4*)(x + ((size_t)b * DIM + c) * 4096);
    int tid = threadIdx.x;
    float s = 0.f;
#pragma unroll
    for (int j = 0; j < 4; j++) {
        float4 v = p[tid + 256 * j];
        s += v.x + v.y + v.z + v.w;
    }
#pragma unroll
    for (int o = 16; o > 0; o >>= 1) s += __shfl_xor_sync(0xFFFFFFFFu, s, o);
    __shared__ float ws[8];
    if ((tid & 31) == 0) ws[tid >> 5] = s;
    __syncthreads();
    if (tid == 0) {
        float t = 0.f;
#pragma unroll
        for (int i = 0; i < 8; i++) t += ws[i];
        g_xavg[b * 256 + c] = t * (1.0f / 4096.0f);
    }
}

// ---------------- K2: avg logits + zero counters ----------------
__global__ void prep_kernel(const float* __restrict__ Wa, const float* __restrict__ ba) {
    int t = threadIdx.x;
    if (t < NE) g_cnt[t] = 0;
    if (t < 128) {
        int b = t >> 3, e = t & 7;
        float acc = 0.f;
        for (int c = 0; c < 256; c++) acc += g_xavg[b * 256 + c] * Wa[c * 8 + e];
        g_avglogit[t] = acc + ba[e];
    }
}

// ---------------- K3: router ----------------
__global__ void router_kernel(const float* __restrict__ x, const float* __restrict__ noise,
                              const float* __restrict__ Wr, const float* __restrict__ br,
                              const float* __restrict__ Wn, const float* __restrict__ bn) {
    __shared__ float sWr[2048], sWn[2048];
    __shared__ float sbr[8], sbn[8], sAvg[8];
    __shared__ int scnt[8], sbase[8];
    int tid = threadIdx.x;
    int i = blockIdx.x * 256 + tid;
    int b = i >> 12;
    for (int j = tid; j < 2048; j += 256) { sWr[j] = Wr[j]; sWn[j] = Wn[j]; }
    if (tid < 8) {
        sbr[tid] = br[tid]; sbn[tid] = bn[tid];
        sAvg[tid] = g_avglogit[b * 8 + tid];
        scnt[tid] = 0;
    }
    __syncthreads();

    float ar[8] = {0, 0, 0, 0, 0, 0, 0, 0};
    float an[8] = {0, 0, 0, 0, 0, 0, 0, 0};
    const float4* xp = (const float4*)(x + (size_t)i * DIM);

#define ROUT_STEP(xc, kk)                                                            \
    {                                                                                \
        float4 w0 = *(const float4*)&sWr[(kk) * 8];                                  \
        float4 w1 = *(const float4*)&sWr[(kk) * 8 + 4];                              \
        float4 u0 = *(const float4*)&sWn[(kk) * 8];                                  \
        float4 u1 = *(const float4*)&sWn[(kk) * 8 + 4];                              \
        ar[0] += (xc) * w0.x; ar[1] += (xc) * w0.y; ar[2] += (xc) * w0.z;            \
        ar[3] += (xc) * w0.w; ar[4] += (xc) * w1.x; ar[5] += (xc) * w1.y;            \
        ar[6] += (xc) * w1.z; ar[7] += (xc) * w1.w;                                  \
        an[0] += (xc) * u0.x; an[1] += (xc) * u0.y; an[2] += (xc) * u0.z;            \
        an[3] += (xc) * u0.w; an[4] += (xc) * u1.x; an[5] += (xc) * u1.y;            \
        an[6] += (xc) * u1.z; an[7] += (xc) * u1.w;                                  \
    }

#pragma unroll 4
    for (int k4 = 0; k4 < 64; k4++) {
        float4 xv = xp[k4];
        int k = k4 * 4;
        ROUT_STEP(xv.x, k + 0);
        ROUT_STEP(xv.y, k + 1);
        ROUT_STEP(xv.z, k + 2);
        ROUT_STEP(xv.w, k + 3);
    }
#undef ROUT_STEP

    float noisy[8];
    const float* np = noise + (size_t)i * 8;
#pragma unroll
    for (int e = 0; e < 8; e++) {
        float lg = ar[e] + sbr[e] + sAvg[e];
        float z = an[e] + sbn[e];
        float sp = fmaxf(z, 0.f) + log1pf(expf(-fabsf(z)));
        noisy[e] = lg + np[e] * sp;
    }
    int i1 = 0; float v1 = noisy[0];
#pragma unroll
    for (int e = 1; e < 8; e++) if (noisy[e] > v1) { v1 = noisy[e]; i1 = e; }
    int i2 = -1; float v2 = -INFINITY;
#pragma unroll
    for (int e = 0; e < 8; e++) if (e != i1 && noisy[e] > v2) { v2 = noisy[e]; i2 = e; }

    float t = expf(v2 - v1);
    int es; float g;
    if (i1 > i2) { es = i1; g = 1.f / (1.f + t); }
    else         { es = i2; g = t / (1.f + t); }

    int pl = atomicAdd(&scnt[es], 1);
    __syncthreads();
    if (tid < 8) sbase[tid] = atomicAdd(&g_cnt[tid], scnt[tid]);
    __syncthreads();
    g_tok[es * NTOK + sbase[es] + pl] = i;
    g_gate[i] = g;
}

// ---------------- K4: per-expert tile offsets ----------------
__global__ void scan_kernel() {
    if (threadIdx.x == 0) {
        int tb = 0;
        for (int e = 0; e < NE; e++) {
            g_tileBase[e] = tb;
            tb += (g_cnt[e] + 127) >> 7;
        }
        g_tileBase[NE] = tb;
    }
}

// ---------------- tile metadata helper ----------------
__device__ __forceinline__ void tile_meta(int bx, int* sMeta) {
    int e = -1, rem = 0, tokbase = 0;
    if (bx < g_tileBase[NE]) {
        e = 0;
        while (bx >= g_tileBase[e + 1]) e++;
        int lt = bx - g_tileBase[e];
        tokbase = e * NTOK + lt * 128;
        rem = g_cnt[e] - lt * 128;
    }
    sMeta[0] = e; sMeta[1] = tokbase; sMeta[2] = rem;
}

// smem layout constants
#define KPAD 36    // A tile: [128][KPAD]  -> fragment loads conflict-free
#define NPAD 132   // B tile: [32][NPAD]   -> staging stores conflict-free

// ================ gemmA: hidden = relu(X @ W1 + b1), tf32 mma.sync ================
__global__ void __launch_bounds__(256, 1)
gemmA_kernel(const float* __restrict__ x, const float* __restrict__ W1,
             const float* __restrict__ b1) {
    __shared__ float As[128 * KPAD];
    __shared__ float Bs[32 * NPAD];
    __shared__ int rowTok[128];
    __shared__ int sMeta[3];

    const int tid = threadIdx.x;
    if (tid == 0) tile_meta(blockIdx.x, sMeta);
    __syncthreads();
    const int e = sMeta[0];
    if (e < 0) return;
    const int rem = sMeta[2];
    const int n0 = blockIdx.y * 128;
    if (tid < 128) rowTok[tid] = (tid < rem) ? g_tok[sMeta[1] + tid] : g_tok[sMeta[1]];
    __syncthreads();

    const int lane = tid & 31, wid = tid >> 5;
    const int wm = wid >> 2, wn = wid & 3;
    const int mbase = wm * 64, nbase = wn * 32;
    const int lr = lane >> 2, lc = lane & 3;

    const float* Wp = W1 + (size_t)e * DIM * HID + n0;

    // staging indices: A: f in 0..7 (16B each), m row; B: k row, n4 quad
    const int am = (tid >> 3) * 4;  // will add i*128? No: handled per-i below
    (void)am;

    float acc[4][4][4];
#pragma unroll
    for (int a = 0; a < 4; a++)
#pragma unroll
        for (int b = 0; b < 4; b++)
#pragma unroll
            for (int c = 0; c < 4; c++) acc[a][b][c] = 0.f;

    float4 Av[4], Bv[4];
    // prefetch chunk 0
#pragma unroll
    for (int i = 0; i < 4; i++) {
        int idx = tid + 256 * i;
        int m = idx >> 3, f = idx & 7;
        Av[i] = *(const float4*)(x + (size_t)rowTok[m] * DIM + f * 4);
    }
#pragma unroll
    for (int i = 0; i < 4; i++) {
        int idx = tid + 256 * i;
        int k = idx >> 5, n4 = idx & 31;
        Bv[i] = *(const float4*)(Wp + (size_t)k * HID + n4 * 4);
    }

    for (int c = 0; c < 8; c++) {
        // store staged regs -> smem (tf32-rounded)
#pragma unroll
        for (int i = 0; i < 4; i++) {
            int idx = tid + 256 * i;
            int m = idx >> 3, f = idx & 7;
            float* d = &As[m * KPAD + f * 4];
            d[0] = __uint_as_float(f2tf(Av[i].x));
            d[1] = __uint_as_float(f2tf(Av[i].y));
            d[2] = __uint_as_float(f2tf(Av[i].z));
            d[3] = __uint_as_float(f2tf(Av[i].w));
        }
#pragma unroll
        for (int i = 0; i < 4; i++) {
            int idx = tid + 256 * i;
            int k = idx >> 5, n4 = idx & 31;
            float* d = &Bs[k * NPAD + n4 * 4];
            d[0] = __uint_as_float(f2tf(Bv[i].x));
            d[1] = __uint_as_float(f2tf(Bv[i].y));
            d[2] = __uint_as_float(f2tf(Bv[i].z));
            d[3] = __uint_as_float(f2tf(Bv[i].w));
        }
        __syncthreads();
        // prefetch next chunk
        if (c < 7) {
            int kt = (c + 1) * 32;
#pragma unroll
            for (int i = 0; i < 4; i++) {
                int idx = tid + 256 * i;
                int m = idx >> 3, f = idx & 7;
                Av[i] = *(const float4*)(x + (size_t)rowTok[m] * DIM + kt + f * 4);
            }
#pragma unroll
            for (int i = 0; i < 4; i++) {
                int idx = tid + 256 * i;
                int k = idx >> 5, n4 = idx & 31;
                Bv[i] = *(const float4*)(Wp + (size_t)(kt + k) * HID + n4 * 4);
            }
        }
        // compute on current smem chunk
#pragma unroll
        for (int ks = 0; ks < 4; ks++) {
            int kk = ks * 8;
            uint32_t af[4][4], bf[4][2];
#pragma unroll
            for (int mt = 0; mt < 4; mt++) {
                const float* p = &As[(mbase + mt * 16 + lr) * KPAD + kk + lc];
                af[mt][0] = __float_as_uint(p[0]);
                af[mt][1] = __float_as_uint(p[8 * KPAD]);
                af[mt][2] = __float_as_uint(p[4]);
                af[mt][3] = __float_as_uint(p[8 * KPAD + 4]);
            }
#pragma unroll
            for (int nt = 0; nt < 4; nt++) {
                const float* p = &Bs[(kk + lc) * NPAD + nbase + nt * 8 + lr];
                bf[nt][0] = __float_as_uint(p[0]);
                bf[nt][1] = __float_as_uint(p[4 * NPAD]);
            }
#pragma unroll
            for (int mt = 0; mt < 4; mt++)
#pragma unroll
                for (int nt = 0; nt < 4; nt++)
                    mma_tf32(acc[mt][nt], af[mt], bf[nt]);
        }
        __syncthreads();
    }

    // epilogue: bias + relu -> g_hidden[tile][m][HID]
    const float* bg = b1 + (size_t)e * HID + n0;
    size_t hrow = (size_t)blockIdx.x * 128;
#pragma unroll
    for (int nt = 0; nt < 4; nt++) {
        int col = nbase + nt * 8 + lc * 2;
        float bb0 = __ldg(bg + col), bb1 = __ldg(bg + col + 1);
#pragma unroll
        for (int mt = 0; mt < 4; mt++) {
            int r0 = mbase + mt * 16 + lr;
            if (r0 < rem) {
                float2 o;
                o.x = fmaxf(acc[mt][nt][0] + bb0, 0.f);
                o.y = fmaxf(acc[mt][nt][1] + bb1, 0.f);
                *(float2*)&g_hidden[(hrow + r0) * HID + n0 + col] = o;
            }
            int r1 = r0 + 8;
            if (r1 < rem) {
                float2 o;
                o.x = fmaxf(acc[mt][nt][2] + bb0, 0.f);
                o.y = fmaxf(acc[mt][nt][3] + bb1, 0.f);
                *(float2*)&g_hidden[(hrow + r1) * HID + n0 + col] = o;
            }
        }
    }
}

// ================ gemmB: out = (hidden @ W2 + b2) * gate, tf32 mma.sync ================
__global__ void __launch_bounds__(256, 1)
gemmB_kernel(const float* __restrict__ W2, const float* __restrict__ b2,
             float* __restrict__ out) {
    __shared__ float As[128 * KPAD];
    __shared__ float Bs[32 * NPAD];
    __shared__ int rowTok[128];
    __shared__ float sGate[128];
    __shared__ int sMeta[3];

    const int tid = threadIdx.x;
    if (tid == 0) tile_meta(blockIdx.x, sMeta);
    __syncthreads();
    const int e = sMeta[0];
    if (e < 0) return;
    const int rem = sMeta[2];
    const int ybase = blockIdx.y * 128;
    if (tid < 128) {
        int tr = (tid < rem) ? g_tok[sMeta[1] + tid] : -1;
        rowTok[tid] = tr;
        sGate[tid] = (tr >= 0) ? g_gate[tr] : 0.f;
    }
    __syncthreads();

    const int lane = tid & 31, wid = tid >> 5;
    const int wm = wid >> 2, wn = wid & 3;
    const int mbase = wm * 64, nbase = wn * 32;
    const int lr = lane >> 2, lc = lane & 3;

    const float* Wp = W2 + (size_t)e * HID * DIM + ybase;
    const float* Hp = g_hidden + (size_t)blockIdx.x * 128 * HID;

    float acc[4][4][4];
#pragma unroll
    for (int a = 0; a < 4; a++)
#pragma unroll
        for (int b = 0; b < 4; b++)
#pragma unroll
            for (int c = 0; c < 4; c++) acc[a][b][c] = 0.f;

    float4 Av[4], Bv[4];
#pragma unroll
    for (int i = 0; i < 4; i++) {
        int idx = tid + 256 * i;
        int m = idx >> 3, f = idx & 7;
        Av[i] = *(const float4*)(Hp + (size_t)m * HID + f * 4);
    }
#pragma unroll
    for (int i = 0; i < 4; i++) {
        int idx = tid + 256 * i;
        int k = idx >> 5, n4 = idx & 31;
        Bv[i] = *(const float4*)(Wp + (size_t)k * DIM + n4 * 4);
    }

    for (int c = 0; c < 32; c++) {
#pragma unroll
        for (int i = 0; i < 4; i++) {
            int idx = tid + 256 * i;
            int m = idx >> 3, f = idx & 7;
            float* d = &As[m * KPAD + f * 4];
            d[0] = __uint_as_float(f2tf(Av[i].x));
            d[1] = __uint_as_float(f2tf(Av[i].y));
            d[2] = __uint_as_float(f2tf(Av[i].z));
            d[3] = __uint_as_float(f2tf(Av[i].w));
        }
#pragma unroll
        for (int i = 0; i < 4; i++) {
            int idx = tid + 256 * i;
            int k = idx >> 5, n4 = idx & 31;
            float* d = &Bs[k * NPAD + n4 * 4];
            d[0] = __uint_as_float(f2tf(Bv[i].x));
            d[1] = __uint_as_float(f2tf(Bv[i].y));
            d[2] = __uint_as_float(f2tf(Bv[i].z));
            d[3] = __uint_as_float(f2tf(Bv[i].w));
        }
        __syncthreads();
        if (c < 31) {
            int kt = (c + 1) * 32;
#pragma unroll
            for (int i = 0; i < 4; i++) {
                int idx = tid + 256 * i;
                int m = idx >> 3, f = idx & 7;
                Av[i] = *(const float4*)(Hp + (size_t)m * HID + kt + f * 4);
            }
#pragma unroll
            for (int i = 0; i < 4; i++) {
                int idx = tid + 256 * i;
                int k = idx >> 5, n4 = idx & 31;
                Bv[i] = *(const float4*)(Wp + (size_t)(kt + k) * DIM + n4 * 4);
            }
        }
#pragma unroll
        for (int ks = 0; ks < 4; ks++) {
            int kk = ks * 8;
            uint32_t af[4][4], bf[4][2];
#pragma unroll
            for (int mt = 0; mt < 4; mt++) {
                const float* p = &As[(mbase + mt * 16 + lr) * KPAD + kk + lc];
                af[mt][0] = __float_as_uint(p[0]);
                af[mt][1] = __float_as_uint(p[8 * KPAD]);
                af[mt][2] = __float_as_uint(p[4]);
                af[mt][3] = __float_as_uint(p[8 * KPAD + 4]);
            }
#pragma unroll
            for (int nt = 0; nt < 4; nt++) {
                const float* p = &Bs[(kk + lc) * NPAD + nbase + nt * 8 + lr];
                bf[nt][0] = __float_as_uint(p[0]);
                bf[nt][1] = __float_as_uint(p[4 * NPAD]);
            }
#pragma unroll
            for (int mt = 0; mt < 4; mt++)
#pragma unroll
                for (int nt = 0; nt < 4; nt++)
                    mma_tf32(acc[mt][nt], af[mt], bf[nt]);
        }
        __syncthreads();
    }

    // epilogue: bias + gate -> scattered out rows
    const float* bg = b2 + (size_t)e * DIM + ybase;
#pragma unroll
    for (int nt = 0; nt < 4; nt++) {
        int col = nbase + nt * 8 + lc * 2;
        float bb0 = __ldg(bg + col), bb1 = __ldg(bg + col + 1);
#pragma unroll
        for (int mt = 0; mt < 4; mt++) {
            int r0 = mbase + mt * 16 + lr;
            if (r0 < rem) {
                float g = sGate[r0];
                float2 o;
                o.x = (acc[mt][nt][0] + bb0) * g;
                o.y = (acc[mt][nt][1] + bb1) * g;
                *(float2*)&out[(size_t)rowTok[r0] * DIM + ybase + col] = o;
            }
            int r1 = r0 + 8;
            if (r1 < rem) {
                float g = sGate[r1];
                float2 o;
                o.x = (acc[mt][nt][2] + bb0) * g;
                o.y = (acc[mt][nt][3] + bb1) * g;
                *(float2*)&out[(size_t)rowTok[r1] * DIM + ybase + col] = o;
            }
        }
    }
}

// ---------------- launch ----------------
extern "C" void kernel_launch(void* const* d_in, const int* in_sizes, int n_in,
                              void* d_out, int out_size) {
    const float* x     = (const float*)d_in[0];
    const float* noise = (const float*)d_in[1];
    const float* Wr    = (const float*)d_in[2];
    const float* br    = (const float*)d_in[3];
    const float* Wa    = (const float*)d_in[4];
    const float* ba    = (const float*)d_in[5];
    const float* Wn    = (const float*)d_in[6];
    const float* bn    = (const float*)d_in[7];
    const float* W1    = (const float*)d_in[8];
    const float* b1    = (const float*)d_in[9];
    const float* W2    = (const float*)d_in[10];
    const float* b2    = (const float*)d_in[11];
    float* out = (float*)d_out;

    avgpool_kernel<<<dim3(256, 16), 256>>>(x);
    prep_kernel<<<1, 128>>>(Wa, ba);
    router_kernel<<<256, 256>>>(x, noise, Wr, br, Wn, bn);
    scan_kernel<<<1, 1>>>();
    gemmA_kernel<<<dim3(MAXTILES, 8), 256>>>(x, W1, b1);
    gemmB_kernel<<<dim3(MAXTILES, 2), 256>>>(W2, b2, out);
}

// round 4
// speedup vs baseline: 2.7635x; 1.1612x over previous
#include <cuda_runtime.h>
#include <cuda_fp16.h>
#include <math.h>
#include <stdint.h>

#define NTOK 65536
#define DIM 256
#define HID 1024
#define NE 8
#define MAXTILES 519

// ---------------- device scratch ----------------
__device__ float g_xavg[16 * 256];
__device__ float g_avglogit[16 * NE];
__device__ int   g_cnt[NE];
__device__ int   g_tileBase[NE + 1];
__device__ int   g_tok[NE * NTOK];
__device__ float g_gate[NTOK];
// hidden per tile, fp16: [tile][m(128)][HID]
__device__ __half g_hidden[(size_t)MAXTILES * 128 * HID];

// ---------------- helpers ----------------
__device__ __forceinline__ uint32_t pk2h(float a, float b) {
    __half2 h = __floats2half2_rn(a, b);
    return *(uint32_t*)&h;
}

__device__ __forceinline__ void mma_f16(float* d, const uint32_t* a, const uint32_t* b) {
    asm volatile(
        "mma.sync.aligned.m16n8k16.row.col.f32.f16.f16.f32 "
        "{%0,%1,%2,%3}, {%4,%5,%6,%7}, {%8,%9}, {%0,%1,%2,%3};"
        : "+f"(d[0]), "+f"(d[1]), "+f"(d[2]), "+f"(d[3])
        : "r"(a[0]), "r"(a[1]), "r"(a[2]), "r"(a[3]), "r"(b[0]), "r"(b[1]));
}

// ---------------- K1: adaptive avg pool over (H,W) ----------------
__global__ void avgpool_kernel(const float* __restrict__ x) {
    int c = blockIdx.x, b = blockIdx.y;
    const float4* p = (const float4*)(x + ((size_t)b * DIM + c) * 4096);
    int tid = threadIdx.x;
    float s = 0.f;
#pragma unroll
    for (int j = 0; j < 4; j++) {
        float4 v = p[tid + 256 * j];
        s += v.x + v.y + v.z + v.w;
    }
#pragma unroll
    for (int o = 16; o > 0; o >>= 1) s += __shfl_xor_sync(0xFFFFFFFFu, s, o);
    __shared__ float ws[8];
    if ((tid & 31) == 0) ws[tid >> 5] = s;
    __syncthreads();
    if (tid == 0) {
        float t = 0.f;
#pragma unroll
        for (int i = 0; i < 8; i++) t += ws[i];
        g_xavg[b * 256 + c] = t * (1.0f / 4096.0f);
    }
}

// ---------------- K2: avg logits + zero counters ----------------
__global__ void prep_kernel(const float* __restrict__ Wa, const float* __restrict__ ba) {
    int t = threadIdx.x;
    if (t < NE) g_cnt[t] = 0;
    if (t < 128) {
        int b = t >> 3, e = t & 7;
        float acc = 0.f;
        for (int c = 0; c < 256; c++) acc += g_xavg[b * 256 + c] * Wa[c * 8 + e];
        g_avglogit[t] = acc + ba[e];
    }
}

// ---------------- K3: router ----------------
__global__ void router_kernel(const float* __restrict__ x, const float* __restrict__ noise,
                              const float* __restrict__ Wr, const float* __restrict__ br,
                              const float* __restrict__ Wn, const float* __restrict__ bn) {
    __shared__ float sWr[2048], sWn[2048];
    __shared__ float sbr[8], sbn[8], sAvg[8];
    __shared__ int scnt[8], sbase[8];
    int tid = threadIdx.x;
    int i = blockIdx.x * 256 + tid;
    int b = i >> 12;
    for (int j = tid; j < 2048; j += 256) { sWr[j] = Wr[j]; sWn[j] = Wn[j]; }
    if (tid < 8) {
        sbr[tid] = br[tid]; sbn[tid] = bn[tid];
        sAvg[tid] = g_avglogit[b * 8 + tid];
        scnt[tid] = 0;
    }
    __syncthreads();

    float ar[8] = {0, 0, 0, 0, 0, 0, 0, 0};
    float an[8] = {0, 0, 0, 0, 0, 0, 0, 0};
    const float4* xp = (const float4*)(x + (size_t)i * DIM);

#define ROUT_STEP(xc, kk)                                                            \
    {                                                                                \
        float4 w0 = *(const float4*)&sWr[(kk) * 8];                                  \
        float4 w1 = *(const float4*)&sWr[(kk) * 8 + 4];                              \
        float4 u0 = *(const float4*)&sWn[(kk) * 8];                                  \
        float4 u1 = *(const float4*)&sWn[(kk) * 8 + 4];                              \
        ar[0] += (xc) * w0.x; ar[1] += (xc) * w0.y; ar[2] += (xc) * w0.z;            \
        ar[3] += (xc) * w0.w; ar[4] += (xc) * w1.x; ar[5] += (xc) * w1.y;            \
        ar[6] += (xc) * w1.z; ar[7] += (xc) * w1.w;                                  \
        an[0] += (xc) * u0.x; an[1] += (xc) * u0.y; an[2] += (xc) * u0.z;            \
        an[3] += (xc) * u0.w; an[4] += (xc) * u1.x; an[5] += (xc) * u1.y;            \
        an[6] += (xc) * u1.z; an[7] += (xc) * u1.w;                                  \
    }

#pragma unroll 4
    for (int k4 = 0; k4 < 64; k4++) {
        float4 xv = xp[k4];
        int k = k4 * 4;
        ROUT_STEP(xv.x, k + 0);
        ROUT_STEP(xv.y, k + 1);
        ROUT_STEP(xv.z, k + 2);
        ROUT_STEP(xv.w, k + 3);
    }
#undef ROUT_STEP

    float noisy[8];
    const float* np = noise + (size_t)i * 8;
#pragma unroll
    for (int e = 0; e < 8; e++) {
        float lg = ar[e] + sbr[e] + sAvg[e];
        float z = an[e] + sbn[e];
        float sp = fmaxf(z, 0.f) + log1pf(expf(-fabsf(z)));
        noisy[e] = lg + np[e] * sp;
    }
    int i1 = 0; float v1 = noisy[0];
#pragma unroll
    for (int e = 1; e < 8; e++) if (noisy[e] > v1) { v1 = noisy[e]; i1 = e; }
    int i2 = -1; float v2 = -INFINITY;
#pragma unroll
    for (int e = 0; e < 8; e++) if (e != i1 && noisy[e] > v2) { v2 = noisy[e]; i2 = e; }

    float t = expf(v2 - v1);
    int es; float g;
    if (i1 > i2) { es = i1; g = 1.f / (1.f + t); }
    else         { es = i2; g = t / (1.f + t); }

    int pl = atomicAdd(&scnt[es], 1);
    __syncthreads();
    if (tid < 8) sbase[tid] = atomicAdd(&g_cnt[tid], scnt[tid]);
    __syncthreads();
    g_tok[es * NTOK + sbase[es] + pl] = i;
    g_gate[i] = g;
}

// ---------------- K4: per-expert tile offsets ----------------
__global__ void scan_kernel() {
    if (threadIdx.x == 0) {
        int tb = 0;
        for (int e = 0; e < NE; e++) {
            g_tileBase[e] = tb;
            tb += (g_cnt[e] + 127) >> 7;
        }
        g_tileBase[NE] = tb;
    }
}

// ---------------- tile metadata helper ----------------
__device__ __forceinline__ void tile_meta(int bx, int* sMeta) {
    int e = -1, rem = 0, tokbase = 0;
    if (bx < g_tileBase[NE]) {
        e = 0;
        while (bx >= g_tileBase[e + 1]) e++;
        int lt = bx - g_tileBase[e];
        tokbase = e * NTOK + lt * 128;
        rem = g_cnt[e] - lt * 128;
    }
    sMeta[0] = e; sMeta[1] = tokbase; sMeta[2] = rem;
}

// Fragment-packed smem:
//  A: [MT(8)][KT(2)] groups of stride 33 u32-quads: ((MT*2+KT)*33+lane)*4 + r
//  B: [NT(16)][KT(2)] groups of stride 33 u32-pairs: ((NT*2+KT)*33+lane)*2 + r
#define ABUF 2112  // u32 per buffer, covers (15*33+31)*4+3
#define BBUF 2112

// inner compute: 2 KT steps, 4x4 m16n8k16
#define COMPUTE_CHUNK(Aup, Bup)                                                   \
    {                                                                             \
        _Pragma("unroll")                                                         \
        for (int KT = 0; KT < 2; KT++) {                                          \
            uint32_t af[4][4], bf[4][2];                                          \
            _Pragma("unroll")                                                     \
            for (int mt = 0; mt < 4; mt++)                                        \
                *(uint4*)af[mt] =                                                 \
                    *(const uint4*)&(Aup)[(((wm * 4 + mt) * 2 + KT) * 33 + lane) * 4]; \
            _Pragma("unroll")                                                     \
            for (int nt = 0; nt < 4; nt++)                                        \
                *(uint2*)bf[nt] =                                                 \
                    *(const uint2*)&(Bup)[(((wn * 4 + nt) * 2 + KT) * 33 + lane) * 2]; \
            _Pragma("unroll")                                                     \
            for (int mt = 0; mt < 4; mt++)                                        \
                _Pragma("unroll")                                                 \
                for (int nt = 0; nt < 4; nt++)                                    \
                    mma_f16(acc[mt][nt], af[mt], bf[nt]);                         \
        }                                                                         \
    }

// ================ gemmA: hidden = relu(X @ W1 + b1), fp16 mma ================
__global__ void __launch_bounds__(256, 1)
gemmA_kernel(const float* __restrict__ x, const float* __restrict__ W1,
             const float* __restrict__ b1) {
    extern __shared__ __align__(16) uint32_t dsm[];
    uint32_t* Au = dsm;             // [2][ABUF]
    uint32_t* Bu = dsm + 2 * ABUF;  // [2][BBUF]
    uint32_t* Hs = dsm + 4 * ABUF;  // [128*68]
    __shared__ int rowTok[128];
    __shared__ int sMeta[3];

    const int tid = threadIdx.x;
    if (tid == 0) tile_meta(blockIdx.x, sMeta);
    __syncthreads();
    const int e = sMeta[0];
    if (e < 0) return;
    const int rem = sMeta[2];
    const int n0 = blockIdx.y * 128;
    if (tid < 128) rowTok[tid] = (tid < rem) ? g_tok[sMeta[1] + tid] : g_tok[sMeta[1]];
    __syncthreads();

    const int lane = tid & 31, wid = tid >> 5;
    const int wm = wid >> 2, wn = wid & 3;
    const int mbase = wm * 64, nbase = wn * 32;
    const int lr = lane >> 2, lc = lane & 3;

    // --- precompute staging pointers/offsets ---
    // A side: 4 float4/thread: idx=tid+256i -> m=idx>>3, j=idx&7 (float4 j -> k=4j)
    const float* arp[4];
    int aofs[4];
#pragma unroll
    for (int i = 0; i < 4; i++) {
        int idx = tid + 256 * i;
        int m = idx >> 3, j = idx & 7;
        arp[i] = x + (size_t)rowTok[m] * DIM + j * 4;
        int MT = m >> 4, KT = j >> 2, s2 = (j >> 1) & 1, lc0 = (j & 1) * 2;
        int r = ((m >> 3) & 1) + 2 * s2;
        aofs[i] = (((MT * 2 + KT) * 33) + (m & 7) * 4 + lc0) * 4 + r;
    }
    // B side: 8 k-pair entries/thread: idx=tid+256i -> kp=idx>>7 (0..15), n=idx&127
    const float* brp[8];
    int bofs[8];
#pragma unroll
    for (int i = 0; i < 8; i++) {
        int idx = tid + 256 * i;
        int kp = idx >> 7, n = idx & 127;
        brp[i] = W1 + (size_t)e * DIM * HID + (size_t)(2 * kp) * HID + n0 + n;
        int KT = kp >> 3, r = (kp & 7) >> 2, lcB = kp & 3, NT = n >> 3;
        bofs[i] = (((NT * 2 + KT) * 33) + (n & 7) * 4 + lcB) * 2 + r;
    }

    float acc[4][4][4];
#pragma unroll
    for (int a = 0; a < 4; a++)
#pragma unroll
        for (int b = 0; b < 4; b++)
#pragma unroll
            for (int c = 0; c < 4; c++) acc[a][b][c] = 0.f;

    float4 Va[4];
    float2 Vb[8];
    // prefetch chunk 0
#pragma unroll
    for (int i = 0; i < 4; i++) Va[i] = *(const float4*)arp[i];
#pragma unroll
    for (int i = 0; i < 8; i++) { Vb[i].x = brp[i][0]; Vb[i].y = brp[i][HID]; }

    for (int c = 0; c < 8; c++) {
        uint32_t* Ab = Au + (c & 1) * ABUF;
        uint32_t* Bb = Bu + (c & 1) * BBUF;
#pragma unroll
        for (int i = 0; i < 4; i++) {
            Ab[aofs[i]] = pk2h(Va[i].x, Va[i].y);
            Ab[aofs[i] + 4] = pk2h(Va[i].z, Va[i].w);
        }
#pragma unroll
        for (int i = 0; i < 8; i++) Bb[bofs[i]] = pk2h(Vb[i].x, Vb[i].y);
        __syncthreads();
        if (c < 7) {
            int kt = (c + 1) * 32;
#pragma unroll
            for (int i = 0; i < 4; i++) Va[i] = *(const float4*)(arp[i] + kt);
            const size_t wo = (size_t)kt * HID;
#pragma unroll
            for (int i = 0; i < 8; i++) { Vb[i].x = brp[i][wo]; Vb[i].y = brp[i][wo + HID]; }
        }
        COMPUTE_CHUNK(Ab, Bb);
    }

    // epilogue: acc -> Hs (half2, row stride 68 u32, conflict-free) -> coalesced STG
    const float* bg = b1 + (size_t)e * HID + n0;
#pragma unroll
    for (int nt = 0; nt < 4; nt++) {
        int col = nbase + nt * 8 + lc * 2;
        float bb0 = __ldg(bg + col), bb1 = __ldg(bg + col + 1);
        int ch = col >> 1;
#pragma unroll
        for (int mt = 0; mt < 4; mt++) {
            int r0 = mbase + mt * 16 + lr;
            Hs[r0 * 68 + ch] = pk2h(fmaxf(acc[mt][nt][0] + bb0, 0.f),
                                    fmaxf(acc[mt][nt][1] + bb1, 0.f));
            Hs[(r0 + 8) * 68 + ch] = pk2h(fmaxf(acc[mt][nt][2] + bb0, 0.f),
                                          fmaxf(acc[mt][nt][3] + bb1, 0.f));
        }
    }
    __syncthreads();
    __half* hp = g_hidden + ((size_t)blockIdx.x * 128) * HID + n0;
#pragma unroll
    for (int j = 0; j < 8; j++) {
        int U = tid + 256 * j;
        int row = U >> 4, c4 = U & 15;
        uint4 v = *(const uint4*)&Hs[row * 68 + c4 * 4];
        *(uint4*)(hp + (size_t)row * HID + c4 * 8) = v;
    }
}

// ================ gemmB: out = (hidden @ W2 + b2) * gate, fp16 mma ================
__global__ void __launch_bounds__(256, 1)
gemmB_kernel(const float* __restrict__ W2, const float* __restrict__ b2,
             float* __restrict__ out) {
    extern __shared__ __align__(16) uint32_t dsm[];
    uint32_t* Au = dsm;
    uint32_t* Bu = dsm + 2 * ABUF;
    __shared__ int rowTok[128];
    __shared__ float sGate[128];
    __shared__ int sMeta[3];

    const int tid = threadIdx.x;
    if (tid == 0) tile_meta(blockIdx.x, sMeta);
    __syncthreads();
    const int e = sMeta[0];
    if (e < 0) return;
    const int rem = sMeta[2];
    const int ybase = blockIdx.y * 128;
    if (tid < 128) {
        int tr = (tid < rem) ? g_tok[sMeta[1] + tid] : -1;
        rowTok[tid] = tr;
        sGate[tid] = (tr >= 0) ? g_gate[tr] : 0.f;
    }
    __syncthreads();

    const int lane = tid & 31, wid = tid >> 5;
    const int wm = wid >> 2, wn = wid & 3;
    const int mbase = wm * 64, nbase = wn * 32;
    const int lr = lane >> 2, lc = lane & 3;

    // A side: hidden (half): 2 uint4/thread: idx=tid+256i -> m=idx>>2, q=idx&3 (k=8q..8q+7)
    const __half* arp[2];
    int aofs[2];
#pragma unroll
    for (int i = 0; i < 2; i++) {
        int idx = tid + 256 * i;
        int m = idx >> 2, q = idx & 3;
        arp[i] = g_hidden + ((size_t)blockIdx.x * 128 + m) * HID + q * 8;
        int MT = m >> 4, KT = q >> 1, s2 = q & 1;
        int r = ((m >> 3) & 1) + 2 * s2;
        aofs[i] = (((MT * 2 + KT) * 33) + (m & 7) * 4) * 4 + r;
    }
    // B side: W2: 8 entries/thread
    const float* brp[8];
    int bofs[8];
#pragma unroll
    for (int i = 0; i < 8; i++) {
        int idx = tid + 256 * i;
        int kp = idx >> 7, n = idx & 127;
        brp[i] = W2 + (size_t)e * HID * DIM + (size_t)(2 * kp) * DIM + ybase + n;
        int KT = kp >> 3, r = (kp & 7) >> 2, lcB = kp & 3, NT = n >> 3;
        bofs[i] = (((NT * 2 + KT) * 33) + (n & 7) * 4 + lcB) * 2 + r;
    }

    float acc[4][4][4];
#pragma unroll
    for (int a = 0; a < 4; a++)
#pragma unroll
        for (int b = 0; b < 4; b++)
#pragma unroll
            for (int c = 0; c < 4; c++) acc[a][b][c] = 0.f;

    uint4 Va[2];
    float2 Vb[8];
#pragma unroll
    for (int i = 0; i < 2; i++) Va[i] = *(const uint4*)arp[i];
#pragma unroll
    for (int i = 0; i < 8; i++) { Vb[i].x = brp[i][0]; Vb[i].y = brp[i][DIM]; }

    for (int c = 0; c < 32; c++) {
        uint32_t* Ab = Au + (c & 1) * ABUF;
        uint32_t* Bb = Bu + (c & 1) * BBUF;
#pragma unroll
        for (int i = 0; i < 2; i++) {
            Ab[aofs[i]] = Va[i].x;
            Ab[aofs[i] + 4] = Va[i].y;
            Ab[aofs[i] + 8] = Va[i].z;
            Ab[aofs[i] + 12] = Va[i].w;
        }
#pragma unroll
        for (int i = 0; i < 8; i++) Bb[bofs[i]] = pk2h(Vb[i].x, Vb[i].y);
        __syncthreads();
        if (c < 31) {
            int kt = (c + 1) * 32;
#pragma unroll
            for (int i = 0; i < 2; i++) Va[i] = *(const uint4*)(arp[i] + kt);
            const size_t wo = (size_t)kt * DIM;
#pragma unroll
            for (int i = 0; i < 8; i++) { Vb[i].x = brp[i][wo]; Vb[i].y = brp[i][wo + DIM]; }
        }
        COMPUTE_CHUNK(Ab, Bb);
    }

    // epilogue: bias + gate -> scattered out rows
    const float* bg = b2 + (size_t)e * DIM + ybase;
#pragma unroll
    for (int nt = 0; nt < 4; nt++) {
        int col = nbase + nt * 8 + lc * 2;
        float bb0 = __ldg(bg + col), bb1 = __ldg(bg + col + 1);
#pragma unroll
        for (int mt = 0; mt < 4; mt++) {
            int r0 = mbase + mt * 16 + lr;
            if (r0 < rem) {
                float g = sGate[r0];
                float2 o;
                o.x = (acc[mt][nt][0] + bb0) * g;
                o.y = (acc[mt][nt][1] + bb1) * g;
                *(float2*)&out[(size_t)rowTok[r0] * DIM + ybase + col] = o;
            }
            int r1 = r0 + 8;
            if (r1 < rem) {
                float g = sGate[r1];
                float2 o;
                o.x = (acc[mt][nt][2] + bb0) * g;
                o.y = (acc[mt][nt][3] + bb1) * g;
                *(float2*)&out[(size_t)rowTok[r1] * DIM + ybase + col] = o;
            }
        }
    }
}

// ---------------- launch ----------------
extern "C" void kernel_launch(void* const* d_in, const int* in_sizes, int n_in,
                              void* d_out, int out_size) {
    const float* x     = (const float*)d_in[0];
    const float* noise = (const float*)d_in[1];
    const float* Wr    = (const float*)d_in[2];
    const float* br    = (const float*)d_in[3];
    const float* Wa    = (const float*)d_in[4];
    const float* ba    = (const float*)d_in[5];
    const float* Wn    = (const float*)d_in[6];
    const float* bn    = (const float*)d_in[7];
    const float* W1    = (const float*)d_in[8];
    const float* b1    = (const float*)d_in[9];
    const float* W2    = (const float*)d_in[10];
    const float* b2    = (const float*)d_in[11];
    float* out = (float*)d_out;

    const int smA = (4 * ABUF + 128 * 68) * 4;  // ~68.6 KB
    const int smB = (4 * ABUF) * 4;             // ~33.8 KB
    static int attr_done = 0;
    if (!attr_done) {
        cudaFuncSetAttribute(gemmA_kernel, cudaFuncAttributeMaxDynamicSharedMemorySize, smA);
        cudaFuncSetAttribute(gemmB_kernel, cudaFuncAttributeMaxDynamicSharedMemorySize, smB);
        attr_done = 1;
    }

    avgpool_kernel<<<dim3(256, 16), 256>>>(x);
    prep_kernel<<<1, 128>>>(Wa, ba);
    router_kernel<<<256, 256>>>(x, noise, Wr, br, Wn, bn);
    scan_kernel<<<1, 1>>>();
    gemmA_kernel<<<dim3(MAXTILES, 8), 256, smA>>>(x, W1, b1);
    gemmB_kernel<<<dim3(MAXTILES, 2), 256, smB>>>(W2, b2, out);
}

// round 7
// speedup vs baseline: 4.1968x; 1.5187x over previous
#include <cuda_runtime.h>
#include <cuda_fp16.h>
#include <math.h>
#include <stdint.h>

#define NTOK 65536
#define DIM 256
#define HID 1024
#define NE 8
#define MAXTILES 519

// ---------------- device scratch ----------------
__device__ float g_xavg[16 * 256];
__device__ float g_avglogit[16 * NE];
__device__ int   g_cnt[NE];
__device__ int   g_tileBase[NE + 1];
__device__ int   g_tok[NE * NTOK];
__device__ float g_gate[NTOK];
__device__ __half g_xh[(size_t)NTOK * DIM];               // fp16 cast of x (token-major)
__device__ __half g_W1h[(size_t)NE * HID * DIM];          // W1 transposed: [e][n(1024)][k(256)]
__device__ __half g_W2h[(size_t)NE * DIM * HID];          // W2 transposed: [e][n(256)][k(1024)]
__device__ __half g_hidden[(size_t)MAXTILES * 128 * HID]; // [tile][m(128)][HID]

// ---------------- helpers ----------------
__device__ __forceinline__ uint32_t pk2h(float a, float b) {
    __half2 h = __floats2half2_rn(a, b);
    return *(uint32_t*)&h;
}

__device__ __forceinline__ void mma_f16(float* d, const uint32_t* a, const uint32_t* b) {
    asm volatile(
        "mma.sync.aligned.m16n8k16.row.col.f32.f16.f16.f32 "
        "{%0,%1,%2,%3}, {%4,%5,%6,%7}, {%8,%9}, {%0,%1,%2,%3};"
        : "+f"(d[0]), "+f"(d[1]), "+f"(d[2]), "+f"(d[3])
        : "r"(a[0]), "r"(a[1]), "r"(a[2]), "r"(a[3]), "r"(b[0]), "r"(b[1]));
}

// ---------------- K0a: x -> fp16 (order-preserving cast) ----------------
__global__ void convX_kernel(const float* __restrict__ x) {
    int i = blockIdx.x * 256 + threadIdx.x;   // per float4
    float4 v = ((const float4*)x)[i];
    uint2 u;
    u.x = pk2h(v.x, v.y);
    u.y = pk2h(v.z, v.w);
    ((uint2*)g_xh)[i] = u;
}

// ---------------- K0b: weight transpose + fp16: W[e][k][n] -> Wt[e][n][k] ----------------
__device__ __forceinline__ void convW_body(const float* __restrict__ W, __half* __restrict__ Wt,
                                           int K, int N) {
    __shared__ float sm[32][33];
    int e = blockIdx.z;
    int n0 = blockIdx.x * 32, k0 = blockIdx.y * 32;
    const float* Wp = W + (size_t)e * K * N;
    __half* Wtp = Wt + (size_t)e * K * N;
    int tx = threadIdx.x, ty = threadIdx.y;  // 32x8
#pragma unroll
    for (int j = 0; j < 4; j++)
        sm[ty + 8 * j][tx] = Wp[(size_t)(k0 + ty + 8 * j) * N + n0 + tx];
    __syncthreads();
#pragma unroll
    for (int j = 0; j < 4; j++)
        Wtp[(size_t)(n0 + ty + 8 * j) * K + k0 + tx] = __float2half(sm[tx][ty + 8 * j]);
}

__global__ void convW1_kernel(const float* __restrict__ W) {
    convW_body(W, g_W1h, DIM, HID);
}
__global__ void convW2_kernel(const float* __restrict__ W) {
    convW_body(W, g_W2h, HID, DIM);
}

// ---------------- K1: adaptive avg pool over (H,W) ----------------
__global__ void avgpool_kernel(const float* __restrict__ x) {
    int c = blockIdx.x, b = blockIdx.y;
    const float4* p = (const float4*)(x + ((size_t)b * DIM + c) * 4096);
    int tid = threadIdx.x;
    float s = 0.f;
#pragma unroll
    for (int j = 0; j < 4; j++) {
        float4 v = p[tid + 256 * j];
        s += v.x + v.y + v.z + v.w;
    }
#pragma unroll
    for (int o = 16; o > 0; o >>= 1) s += __shfl_xor_sync(0xFFFFFFFFu, s, o);
    __shared__ float ws[8];
    if ((tid & 31) == 0) ws[tid >> 5] = s;
    __syncthreads();
    if (tid == 0) {
        float t = 0.f;
#pragma unroll
        for (int i = 0; i < 8; i++) t += ws[i];
        g_xavg[b * 256 + c] = t * (1.0f / 4096.0f);
    }
}

// ---------------- K2: avg logits + zero counters ----------------
__global__ void prep_kernel(const float* __restrict__ Wa, const float* __restrict__ ba) {
    int t = threadIdx.x;
    if (t < NE) g_cnt[t] = 0;
    if (t < 128) {
        int b = t >> 3, e = t & 7;
        float acc = 0.f;
        for (int c = 0; c < 256; c++) acc += g_xavg[b * 256 + c] * Wa[c * 8 + e];
        g_avglogit[t] = acc + ba[e];
    }
}

// ---------------- K3: router ----------------
__global__ void router_kernel(const float* __restrict__ x, const float* __restrict__ noise,
                              const float* __restrict__ Wr, const float* __restrict__ br,
                              const float* __restrict__ Wn, const float* __restrict__ bn) {
    __shared__ float sWr[2048], sWn[2048];
    __shared__ float sbr[8], sbn[8], sAvg[8];
    __shared__ int scnt[8], sbase[8];
    int tid = threadIdx.x;
    int i = blockIdx.x * 256 + tid;
    int b = i >> 12;
    for (int j = tid; j < 2048; j += 256) { sWr[j] = Wr[j]; sWn[j] = Wn[j]; }
    if (tid < 8) {
        sbr[tid] = br[tid]; sbn[tid] = bn[tid];
        sAvg[tid] = g_avglogit[b * 8 + tid];
        scnt[tid] = 0;
    }
    __syncthreads();

    float ar[8] = {0, 0, 0, 0, 0, 0, 0, 0};
    float an[8] = {0, 0, 0, 0, 0, 0, 0, 0};
    const float4* xp = (const float4*)(x + (size_t)i * DIM);

#define ROUT_STEP(xc, kk)                                                            \
    {                                                                                \
        float4 w0 = *(const float4*)&sWr[(kk) * 8];                                  \
        float4 w1 = *(const float4*)&sWr[(kk) * 8 + 4];                              \
        float4 u0 = *(const float4*)&sWn[(kk) * 8];                                  \
        float4 u1 = *(const float4*)&sWn[(kk) * 8 + 4];                              \
        ar[0] += (xc) * w0.x; ar[1] += (xc) * w0.y; ar[2] += (xc) * w0.z;            \
        ar[3] += (xc) * w0.w; ar[4] += (xc) * w1.x; ar[5] += (xc) * w1.y;            \
        ar[6] += (xc) * w1.z; ar[7] += (xc) * w1.w;                                  \
        an[0] += (xc) * u0.x; an[1] += (xc) * u0.y; an[2] += (xc) * u0.z;            \
        an[3] += (xc) * u0.w; an[4] += (xc) * u1.x; an[5] += (xc) * u1.y;            \
        an[6] += (xc) * u1.z; an[7] += (xc) * u1.w;                                  \
    }

#pragma unroll 4
    for (int k4 = 0; k4 < 64; k4++) {
        float4 xv = xp[k4];
        int k = k4 * 4;
        ROUT_STEP(xv.x, k + 0);
        ROUT_STEP(xv.y, k + 1);
        ROUT_STEP(xv.z, k + 2);
        ROUT_STEP(xv.w, k + 3);
    }
#undef ROUT_STEP

    float noisy[8];
    const float* np = noise + (size_t)i * 8;
#pragma unroll
    for (int e = 0; e < 8; e++) {
        float lg = ar[e] + sbr[e] + sAvg[e];
        float z = an[e] + sbn[e];
        float sp = fmaxf(z, 0.f) + log1pf(expf(-fabsf(z)));
        noisy[e] = lg + np[e] * sp;
    }
    int i1 = 0; float v1 = noisy[0];
#pragma unroll
    for (int e = 1; e < 8; e++) if (noisy[e] > v1) { v1 = noisy[e]; i1 = e; }
    int i2 = -1; float v2 = -INFINITY;
#pragma unroll
    for (int e = 0; e < 8; e++) if (e != i1 && noisy[e] > v2) { v2 = noisy[e]; i2 = e; }

    float t = expf(v2 - v1);
    int es; float g;
    if (i1 > i2) { es = i1; g = 1.f / (1.f + t); }
    else         { es = i2; g = t / (1.f + t); }

    int pl = atomicAdd(&scnt[es], 1);
    __syncthreads();
    if (tid < 8) sbase[tid] = atomicAdd(&g_cnt[tid], scnt[tid]);
    __syncthreads();
    g_tok[es * NTOK + sbase[es] + pl] = i;
    g_gate[i] = g;
}

// ---------------- K4: per-expert tile offsets ----------------
__global__ void scan_kernel() {
    if (threadIdx.x == 0) {
        int tb = 0;
        for (int e = 0; e < NE; e++) {
            g_tileBase[e] = tb;
            tb += (g_cnt[e] + 127) >> 7;
        }
        g_tileBase[NE] = tb;
    }
}

// ---------------- tile metadata helper ----------------
__device__ __forceinline__ void tile_meta(int bx, int* sMeta) {
    int e = -1, rem = 0, tokbase = 0;
    if (bx < g_tileBase[NE]) {
        e = 0;
        while (bx >= g_tileBase[e + 1]) e++;
        int lt = bx - g_tileBase[e];
        tokbase = e * NTOK + lt * 128;
        rem = g_cnt[e] - lt * 128;
    }
    sMeta[0] = e; sMeta[1] = tokbase; sMeta[2] = rem;
}

// Fragment-packed smem (u32 units):
//  A: [MT(8)][KT(2)] groups, addr = ((MT*2+KT)*33 + lane)*4 + r
//  B: [NT(16)][KT(2)] groups, addr = ((NT*2+KT)*33 + lane)*2 + r
#define ABUF 2112
#define BBUF 2112

#define COMPUTE_CHUNK(Aup, Bup)                                                   \
    {                                                                             \
        _Pragma("unroll")                                                         \
        for (int KT = 0; KT < 2; KT++) {                                          \
            uint32_t af[4][4], bf[4][2];                                          \
            _Pragma("unroll")                                                     \
            for (int mt = 0; mt < 4; mt++)                                        \
                *(uint4*)af[mt] =                                                 \
                    *(const uint4*)&(Aup)[(((wm * 4 + mt) * 2 + KT) * 33 + lane) * 4]; \
            _Pragma("unroll")                                                     \
            for (int nt = 0; nt < 4; nt++)                                        \
                *(uint2*)bf[nt] =                                                 \
                    *(const uint2*)&(Bup)[(((wn * 4 + nt) * 2 + KT) * 33 + lane) * 2]; \
            _Pragma("unroll")                                                     \
            for (int mt = 0; mt < 4; mt++)                                        \
                _Pragma("unroll")                                                 \
                for (int nt = 0; nt < 4; nt++)                                    \
                    mma_f16(acc[mt][nt], af[mt], bf[nt]);                         \
        }                                                                         \
    }

// ================ gemmA: hidden = relu(X @ W1 + b1) ================
__global__ void __launch_bounds__(256, 2)
gemmA_kernel(const float* __restrict__ b1) {
    extern __shared__ __align__(16) uint32_t dsm[];
    uint32_t* Au = dsm;             // [2][ABUF]
    uint32_t* Bu = dsm + 2 * ABUF;  // [2][BBUF]
    uint32_t* Hs = dsm + 4 * ABUF;  // [128*68]
    __shared__ int rowTok[128];
    __shared__ int sMeta[3];

    const int tid = threadIdx.x;
    if (tid == 0) tile_meta(blockIdx.x, sMeta);
    __syncthreads();
    const int e = sMeta[0];
    if (e < 0) return;
    const int rem = sMeta[2];
    const int n0 = blockIdx.y * 128;
    if (tid < 128) rowTok[tid] = (tid < rem) ? g_tok[sMeta[1] + tid] : g_tok[sMeta[1]];
    __syncthreads();

    const int lane = tid & 31, wid = tid >> 5;
    const int wm = wid >> 2, wn = wid & 3;
    const int mbase = wm * 64, nbase = wn * 32;
    const int lr = lane >> 2, lc = lane & 3;

    const __half* arp[2];
    const __half* brp[2];
    int aofs[2], bofs[2];
#pragma unroll
    for (int i = 0; i < 2; i++) {
        int idx = tid + 256 * i;
        int m = idx >> 2, q = idx & 3;
        arp[i] = g_xh + (size_t)rowTok[m] * DIM + q * 8;
        int MT = m >> 4, KT = q >> 1;
        aofs[i] = (((MT * 2 + KT) * 33) + (m & 7) * 4) * 4 + ((m >> 3) & 1) + 2 * (q & 1);
        int n = idx >> 2;  // same decomposition for B
        brp[i] = g_W1h + (size_t)e * HID * DIM + (size_t)(n0 + n) * DIM + q * 8;
        int NT = n >> 3;
        bofs[i] = (((NT * 2 + KT) * 33) + (n & 7) * 4) * 2 + (q & 1);
    }

    float acc[4][4][4];
#pragma unroll
    for (int a = 0; a < 4; a++)
#pragma unroll
        for (int b = 0; b < 4; b++)
#pragma unroll
            for (int c = 0; c < 4; c++) acc[a][b][c] = 0.f;

    uint4 Va[2], Vb[2];
#pragma unroll
    for (int i = 0; i < 2; i++) {
        Va[i] = *(const uint4*)arp[i];
        Vb[i] = *(const uint4*)brp[i];
    }

    for (int c = 0; c < 8; c++) {
        uint32_t* Ab = Au + (c & 1) * ABUF;
        uint32_t* Bb = Bu + (c & 1) * BBUF;
#pragma unroll
        for (int i = 0; i < 2; i++) {
            Ab[aofs[i]] = Va[i].x;  Ab[aofs[i] + 4] = Va[i].y;
            Ab[aofs[i] + 8] = Va[i].z;  Ab[aofs[i] + 12] = Va[i].w;
            Bb[bofs[i]] = Vb[i].x;  Bb[bofs[i] + 2] = Vb[i].y;
            Bb[bofs[i] + 4] = Vb[i].z;  Bb[bofs[i] + 6] = Vb[i].w;
        }
        __syncthreads();
        if (c < 7) {
            int kt = (c + 1) * 32;
#pragma unroll
            for (int i = 0; i < 2; i++) {
                Va[i] = *(const uint4*)(arp[i] + kt);
                Vb[i] = *(const uint4*)(brp[i] + kt);
            }
        }
        COMPUTE_CHUNK(Ab, Bb);
    }

    // epilogue: acc -> Hs (half2, row stride 68 u32) -> coalesced STG
    const float* bg = b1 + (size_t)e * HID + n0;
#pragma unroll
    for (int nt = 0; nt < 4; nt++) {
        int col = nbase + nt * 8 + lc * 2;
        float bb0 = __ldg(bg + col), bb1 = __ldg(bg + col + 1);
        int ch = col >> 1;
#pragma unroll
        for (int mt = 0; mt < 4; mt++) {
            int r0 = mbase + mt * 16 + lr;
            Hs[r0 * 68 + ch] = pk2h(fmaxf(acc[mt][nt][0] + bb0, 0.f),
                                    fmaxf(acc[mt][nt][1] + bb1, 0.f));
            Hs[(r0 + 8) * 68 + ch] = pk2h(fmaxf(acc[mt][nt][2] + bb0, 0.f),
                                          fmaxf(acc[mt][nt][3] + bb1, 0.f));
        }
    }
    __syncthreads();
    __half* hp = g_hidden + ((size_t)blockIdx.x * 128) * HID + n0;
#pragma unroll
    for (int j = 0; j < 8; j++) {
        int U = tid + 256 * j;
        int row = U >> 4, c4 = U & 15;
        uint4 v = *(const uint4*)&Hs[row * 68 + c4 * 4];
        *(uint4*)(hp + (size_t)row * HID + c4 * 8) = v;
    }
}

// ================ gemmB: out = (hidden @ W2 + b2) * gate ================
__global__ void __launch_bounds__(256, 2)
gemmB_kernel(const float* __restrict__ b2, float* __restrict__ out) {
    extern __shared__ __align__(16) uint32_t dsm[];
    uint32_t* Au = dsm;
    uint32_t* Bu = dsm + 2 * ABUF;
    __shared__ int rowTok[128];
    __shared__ float sGate[128];
    __shared__ int sMeta[3];

    const int tid = threadIdx.x;
    if (tid == 0) tile_meta(blockIdx.x, sMeta);
    __syncthreads();
    const int e = sMeta[0];
    if (e < 0) return;
    const int rem = sMeta[2];
    const int ybase = blockIdx.y * 128;
    if (tid < 128) {
        int tr = (tid < rem) ? g_tok[sMeta[1] + tid] : -1;
        rowTok[tid] = tr;
        sGate[tid] = (tr >= 0) ? g_gate[tr] : 0.f;
    }
    __syncthreads();

    const int lane = tid & 31, wid = tid >> 5;
    const int wm = wid >> 2, wn = wid & 3;
    const int mbase = wm * 64, nbase = wn * 32;
    const int lr = lane >> 2, lc = lane & 3;

    const __half* arp[2];
    const __half* brp[2];
    int aofs[2], bofs[2];
#pragma unroll
    for (int i = 0; i < 2; i++) {
        int idx = tid + 256 * i;
        int m = idx >> 2, q = idx & 3;
        arp[i] = g_hidden + ((size_t)blockIdx.x * 128 + m) * HID + q * 8;
        int MT = m >> 4, KT = q >> 1;
        aofs[i] = (((MT * 2 + KT) * 33) + (m & 7) * 4) * 4 + ((m >> 3) & 1) + 2 * (q & 1);
        int n = idx >> 2;
        brp[i] = g_W2h + (size_t)e * DIM * HID + (size_t)(ybase + n) * HID + q * 8;
        int NT = n >> 3;
        bofs[i] = (((NT * 2 + KT) * 33) + (n & 7) * 4) * 2 + (q & 1);
    }

    float acc[4][4][4];
#pragma unroll
    for (int a = 0; a < 4; a++)
#pragma unroll
        for (int b = 0; b < 4; b++)
#pragma unroll
            for (int c = 0; c < 4; c++) acc[a][b][c] = 0.f;

    uint4 Va[2], Vb[2];
#pragma unroll
    for (int i = 0; i < 2; i++) {
        Va[i] = *(const uint4*)arp[i];
        Vb[i] = *(const uint4*)brp[i];
    }

    for (int c = 0; c < 32; c++) {
        uint32_t* Ab = Au + (c & 1) * ABUF;
        uint32_t* Bb = Bu + (c & 1) * BBUF;
#pragma unroll
        for (int i = 0; i < 2; i++) {
            Ab[aofs[i]] = Va[i].x;  Ab[aofs[i] + 4] = Va[i].y;
            Ab[aofs[i] + 8] = Va[i].z;  Ab[aofs[i] + 12] = Va[i].w;
            Bb[bofs[i]] = Vb[i].x;  Bb[bofs[i] + 2] = Vb[i].y;
            Bb[bofs[i] + 4] = Vb[i].z;  Bb[bofs[i] + 6] = Vb[i].w;
        }
        __syncthreads();
        if (c < 31) {
            int kt = (c + 1) * 32;
#pragma unroll
            for (int i = 0; i < 2; i++) {
                Va[i] = *(const uint4*)(arp[i] + kt);
                Vb[i] = *(const uint4*)(brp[i] + kt);
            }
        }
        COMPUTE_CHUNK(Ab, Bb);
    }

    // epilogue: bias + gate -> scattered out rows
    const float* bg = b2 + (size_t)e * DIM + ybase;
#pragma unroll
    for (int nt = 0; nt < 4; nt++) {
        int col = nbase + nt * 8 + lc * 2;
        float bb0 = __ldg(bg + col), bb1 = __ldg(bg + col + 1);
#pragma unroll
        for (int mt = 0; mt < 4; mt++) {
            int r0 = mbase + mt * 16 + lr;
            if (r0 < rem) {
                float g = sGate[r0];
                float2 o;
                o.x = (acc[mt][nt][0] + bb0) * g;
                o.y = (acc[mt][nt][1] + bb1) * g;
                *(float2*)&out[(size_t)rowTok[r0] * DIM + ybase + col] = o;
            }
            int r1 = r0 + 8;
            if (r1 < rem) {
                float g = sGate[r1];
                float2 o;
                o.x = (acc[mt][nt][2] + bb0) * g;
                o.y = (acc[mt][nt][3] + bb1) * g;
                *(float2*)&out[(size_t)rowTok[r1] * DIM + ybase + col] = o;
            }
        }
    }
}

// ---------------- launch ----------------
extern "C" void kernel_launch(void* const* d_in, const int* in_sizes, int n_in,
                              void* d_out, int out_size) {
    const float* x     = (const float*)d_in[0];
    const float* noise = (const float*)d_in[1];
    const float* Wr    = (const float*)d_in[2];
    const float* br    = (const float*)d_in[3];
    const float* Wa    = (const float*)d_in[4];
    const float* ba    = (const float*)d_in[5];
    const float* Wn    = (const float*)d_in[6];
    const float* bn    = (const float*)d_in[7];
    const float* W1    = (const float*)d_in[8];
    const float* b1    = (const float*)d_in[9];
    const float* W2    = (const float*)d_in[10];
    const float* b2    = (const float*)d_in[11];
    float* out = (float*)d_out;

    const int smA = (4 * ABUF + 128 * 68) * 4;  // 68.6 KB
    const int smB = (4 * ABUF) * 4;             // 33.8 KB
    cudaFuncSetAttribute(gemmA_kernel, cudaFuncAttributeMaxDynamicSharedMemorySize, smA);
    cudaFuncSetAttribute(gemmB_kernel, cudaFuncAttributeMaxDynamicSharedMemorySize, smB);

    convX_kernel<<<NTOK * DIM / 4 / 256, 256>>>(x);
    convW1_kernel<<<dim3(HID / 32, DIM / 32, NE), dim3(32, 8)>>>(W1);
    convW2_kernel<<<dim3(DIM / 32, HID / 32, NE), dim3(32, 8)>>>(W2);
    avgpool_kernel<<<dim3(256, 16), 256>>>(x);
    prep_kernel<<<1, 128>>>(Wa, ba);
    router_kernel<<<256, 256>>>(x, noise, Wr, br, Wn, bn);
    scan_kernel<<<1, 1>>>();
    gemmA_kernel<<<dim3(MAXTILES, 8), 256, smA>>>(b1);
    gemmB_kernel<<<dim3(MAXTILES, 2), 256, smB>>>(b2, out);
}

// round 8
// speedup vs baseline: 5.1612x; 1.2298x over previous
#include <cuda_runtime.h>
#include <cuda_fp16.h>
#include <math.h>
#include <stdint.h>

#define NTOK 65536
#define DIM 256
#define HID 1024
#define NE 8
#define MAXTILES 519

// ---------------- device scratch ----------------
__device__ float g_xavg[16 * 256];
__device__ float g_avglogit[16 * NE];
__device__ int   g_cnt[NE];
__device__ int   g_tileBase[NE + 1];
__device__ int   g_tok[NE * NTOK];
__device__ float g_gate[NTOK];
__device__ __half g_xh[(size_t)NTOK * DIM];               // fp16 cast of x (token-major)
__device__ __half g_W1h[(size_t)NE * HID * DIM];          // W1 transposed: [e][n(1024)][k(256)]
__device__ __half g_W2h[(size_t)NE * DIM * HID];          // W2 transposed: [e][n(256)][k(1024)]
__device__ __half g_hidden[(size_t)MAXTILES * 128 * HID]; // [tile][m(128)][HID]

// ---------------- helpers ----------------
__device__ __forceinline__ uint32_t pk2h(float a, float b) {
    __half2 h = __floats2half2_rn(a, b);
    return *(uint32_t*)&h;
}
__device__ __forceinline__ uint32_t smem_u32(const void* p) {
    uint32_t a;
    asm("{ .reg .u64 t; cvta.to.shared.u64 t, %1; cvt.u32.u64 %0, t; }" : "=r"(a) : "l"(p));
    return a;
}
__device__ __forceinline__ void mma_f16(float* d, const uint32_t* a, const uint32_t* b) {
    asm volatile(
        "mma.sync.aligned.m16n8k16.row.col.f32.f16.f16.f32 "
        "{%0,%1,%2,%3}, {%4,%5,%6,%7}, {%8,%9}, {%0,%1,%2,%3};"
        : "+f"(d[0]), "+f"(d[1]), "+f"(d[2]), "+f"(d[3])
        : "r"(a[0]), "r"(a[1]), "r"(a[2]), "r"(a[3]), "r"(b[0]), "r"(b[1]));
}
__device__ __forceinline__ void cpa16(uint32_t dst, const void* src) {
    asm volatile("cp.async.cg.shared.global [%0], [%1], 16;" :: "r"(dst), "l"(src));
}
#define CP_COMMIT() asm volatile("cp.async.commit_group;" ::: "memory")
#define CP_WAIT1()  asm volatile("cp.async.wait_group 1;" ::: "memory")
__device__ __forceinline__ void ldsm4(uint32_t* r, uint32_t addr) {
    asm volatile("ldmatrix.sync.aligned.m8n8.x4.shared.b16 {%0,%1,%2,%3}, [%4];"
                 : "=r"(r[0]), "=r"(r[1]), "=r"(r[2]), "=r"(r[3]) : "r"(addr));
}
__device__ __forceinline__ void ldsm2(uint32_t* r, uint32_t addr) {
    asm volatile("ldmatrix.sync.aligned.m8n8.x2.shared.b16 {%0,%1}, [%2];"
                 : "=r"(r[0]), "=r"(r[1]) : "r"(addr));
}

// ---------------- K0a: x -> fp16 (order-preserving cast) ----------------
__global__ void convX_kernel(const float* __restrict__ x) {
    int i = blockIdx.x * 256 + threadIdx.x;
    float4 v = ((const float4*)x)[i];
    uint2 u;
    u.x = pk2h(v.x, v.y);
    u.y = pk2h(v.z, v.w);
    ((uint2*)g_xh)[i] = u;
}

// ---------------- K0b: weight transpose + fp16: W[e][k][n] -> Wt[e][n][k] ----------------
__device__ __forceinline__ void convW_body(const float* __restrict__ W, __half* __restrict__ Wt,
                                           int K, int N) {
    __shared__ float sm[32][33];
    int e = blockIdx.z;
    int n0 = blockIdx.x * 32, k0 = blockIdx.y * 32;
    const float* Wp = W + (size_t)e * K * N;
    __half* Wtp = Wt + (size_t)e * K * N;
    int tx = threadIdx.x, ty = threadIdx.y;
#pragma unroll
    for (int j = 0; j < 4; j++)
        sm[ty + 8 * j][tx] = Wp[(size_t)(k0 + ty + 8 * j) * N + n0 + tx];
    __syncthreads();
#pragma unroll
    for (int j = 0; j < 4; j++)
        Wtp[(size_t)(n0 + ty + 8 * j) * K + k0 + tx] = __float2half(sm[tx][ty + 8 * j]);
}
__global__ void convW1_kernel(const float* __restrict__ W) { convW_body(W, g_W1h, DIM, HID); }
__global__ void convW2_kernel(const float* __restrict__ W) { convW_body(W, g_W2h, HID, DIM); }

// ---------------- K1: adaptive avg pool over (H,W) ----------------
__global__ void avgpool_kernel(const float* __restrict__ x) {
    int c = blockIdx.x, b = blockIdx.y;
    const float4* p = (const float4*)(x + ((size_t)b * DIM + c) * 4096);
    int tid = threadIdx.x;
    float s = 0.f;
#pragma unroll
    for (int j = 0; j < 4; j++) {
        float4 v = p[tid + 256 * j];
        s += v.x + v.y + v.z + v.w;
    }
#pragma unroll
    for (int o = 16; o > 0; o >>= 1) s += __shfl_xor_sync(0xFFFFFFFFu, s, o);
    __shared__ float ws[8];
    if ((tid & 31) == 0) ws[tid >> 5] = s;
    __syncthreads();
    if (tid == 0) {
        float t = 0.f;
#pragma unroll
        for (int i = 0; i < 8; i++) t += ws[i];
        g_xavg[b * 256 + c] = t * (1.0f / 4096.0f);
    }
}

// ---------------- K2: avg logits + zero counters ----------------
__global__ void prep_kernel(const float* __restrict__ Wa, const float* __restrict__ ba) {
    int t = threadIdx.x;
    if (t < NE) g_cnt[t] = 0;
    if (t < 128) {
        int b = t >> 3, e = t & 7;
        float acc = 0.f;
        for (int c = 0; c < 256; c++) acc += g_xavg[b * 256 + c] * Wa[c * 8 + e];
        g_avglogit[t] = acc + ba[e];
    }
}

// ---------------- K3: router ----------------
__global__ void router_kernel(const float* __restrict__ x, const float* __restrict__ noise,
                              const float* __restrict__ Wr, const float* __restrict__ br,
                              const float* __restrict__ Wn, const float* __restrict__ bn) {
    __shared__ float sWr[2048], sWn[2048];
    __shared__ float sbr[8], sbn[8], sAvg[8];
    __shared__ int scnt[8], sbase[8];
    int tid = threadIdx.x;
    int i = blockIdx.x * 256 + tid;
    int b = i >> 12;
    for (int j = tid; j < 2048; j += 256) { sWr[j] = Wr[j]; sWn[j] = Wn[j]; }
    if (tid < 8) {
        sbr[tid] = br[tid]; sbn[tid] = bn[tid];
        sAvg[tid] = g_avglogit[b * 8 + tid];
        scnt[tid] = 0;
    }
    __syncthreads();

    float ar[8] = {0, 0, 0, 0, 0, 0, 0, 0};
    float an[8] = {0, 0, 0, 0, 0, 0, 0, 0};
    const float4* xp = (const float4*)(x + (size_t)i * DIM);

#define ROUT_STEP(xc, kk)                                                            \
    {                                                                                \
        float4 w0 = *(const float4*)&sWr[(kk) * 8];                                  \
        float4 w1 = *(const float4*)&sWr[(kk) * 8 + 4];                              \
        float4 u0 = *(const float4*)&sWn[(kk) * 8];                                  \
        float4 u1 = *(const float4*)&sWn[(kk) * 8 + 4];                              \
        ar[0] += (xc) * w0.x; ar[1] += (xc) * w0.y; ar[2] += (xc) * w0.z;            \
        ar[3] += (xc) * w0.w; ar[4] += (xc) * w1.x; ar[5] += (xc) * w1.y;            \
        ar[6] += (xc) * w1.z; ar[7] += (xc) * w1.w;                                  \
        an[0] += (xc) * u0.x; an[1] += (xc) * u0.y; an[2] += (xc) * u0.z;            \
        an[3] += (xc) * u0.w; an[4] += (xc) * u1.x; an[5] += (xc) * u1.y;            \
        an[6] += (xc) * u1.z; an[7] += (xc) * u1.w;                                  \
    }

#pragma unroll 4
    for (int k4 = 0; k4 < 64; k4++) {
        float4 xv = xp[k4];
        int k = k4 * 4;
        ROUT_STEP(xv.x, k + 0);
        ROUT_STEP(xv.y, k + 1);
        ROUT_STEP(xv.z, k + 2);
        ROUT_STEP(xv.w, k + 3);
    }
#undef ROUT_STEP

    float noisy[8];
    const float* np = noise + (size_t)i * 8;
#pragma unroll
    for (int e = 0; e < 8; e++) {
        float lg = ar[e] + sbr[e] + sAvg[e];
        float z = an[e] + sbn[e];
        float sp = fmaxf(z, 0.f) + log1pf(expf(-fabsf(z)));
        noisy[e] = lg + np[e] * sp;
    }
    int i1 = 0; float v1 = noisy[0];
#pragma unroll
    for (int e = 1; e < 8; e++) if (noisy[e] > v1) { v1 = noisy[e]; i1 = e; }
    int i2 = -1; float v2 = -INFINITY;
#pragma unroll
    for (int e = 0; e < 8; e++) if (e != i1 && noisy[e] > v2) { v2 = noisy[e]; i2 = e; }

    float t = expf(v2 - v1);
    int es; float g;
    if (i1 > i2) { es = i1; g = 1.f / (1.f + t); }
    else         { es = i2; g = t / (1.f + t); }

    int pl = atomicAdd(&scnt[es], 1);
    __syncthreads();
    if (tid < 8) sbase[tid] = atomicAdd(&g_cnt[tid], scnt[tid]);
    __syncthreads();
    g_tok[es * NTOK + sbase[es] + pl] = i;
    g_gate[i] = g;
}

// ---------------- K4: per-expert tile offsets ----------------
__global__ void scan_kernel() {
    if (threadIdx.x == 0) {
        int tb = 0;
        for (int e = 0; e < NE; e++) {
            g_tileBase[e] = tb;
            tb += (g_cnt[e] + 127) >> 7;
        }
        g_tileBase[NE] = tb;
    }
}

// ---------------- tile metadata helper ----------------
__device__ __forceinline__ void tile_meta(int bx, int* sMeta) {
    int e = -1, rem = 0, tokbase = 0;
    if (bx < g_tileBase[NE]) {
        e = 0;
        while (bx >= g_tileBase[e + 1]) e++;
        int lt = bx - g_tileBase[e];
        tokbase = e * NTOK + lt * 128;
        rem = g_cnt[e] - lt * 128;
    }
    sMeta[0] = e; sMeta[1] = tokbase; sMeta[2] = rem;
}

// ==================== GEMM core: cp.async + ldmatrix, BK=64, 3 stages ====================
// Stage layout (bytes): A tile [128 rows][128 B] SW128-swizzled at +0;
//                       B tile [128 rows][128 B] at +16384. Stage stride 32768.
// Swizzle: 16B-chunk index ch stored at (ch ^ (row & 7)).
#define STAGE_BYTES 32768
#define SMEM_GEMM (3 * STAGE_BYTES)  // 96 KB

#define GEMM_LOAD(st, cc)                                                     \
    do {                                                                      \
        uint32_t _ab = smemBase + (st) * STAGE_BYTES;                         \
        int _kt = (cc) * 64;                                                  \
        _Pragma("unroll")                                                     \
        for (int i = 0; i < 4; i++) cpa16(_ab + aDst[i], aSrc[i] + _kt);      \
        _Pragma("unroll")                                                     \
        for (int i = 0; i < 4; i++) cpa16(_ab + bDst[i], bSrc[i] + _kt);      \
    } while (0)

#define GEMM_COMPUTE(st)                                                      \
    do {                                                                      \
        uint32_t _ab = smemBase + (st) * STAGE_BYTES;                         \
        _Pragma("unroll")                                                     \
        for (int ks = 0; ks < 4; ks++) {                                      \
            uint32_t af[4][4], bf[4][2];                                      \
            _Pragma("unroll")                                                 \
            for (int mt = 0; mt < 4; mt++)                                    \
                ldsm4(af[mt], _ab + aLdBase + mt * 2048 +                     \
                              ((uint32_t)((2 * ks + hiA) ^ r7A) << 4));       \
            _Pragma("unroll")                                                 \
            for (int nt = 0; nt < 4; nt++)                                    \
                ldsm2(bf[nt], _ab + 16384 + bLdBase + nt * 1024 +             \
                              ((uint32_t)((2 * ks + hiB) ^ r7B) << 4));       \
            _Pragma("unroll")                                                 \
            for (int mt = 0; mt < 4; mt++)                                    \
                _Pragma("unroll")                                             \
                for (int nt = 0; nt < 4; nt++)                                \
                    mma_f16(acc[mt][nt], af[mt], bf[nt]);                     \
        }                                                                     \
    } while (0)

// ================ gemmA: hidden = relu(X @ W1 + b1) ================
__global__ void __launch_bounds__(256, 2)
gemmA_kernel(const float* __restrict__ b1) {
    extern __shared__ __align__(16) char dsm[];
    __shared__ int rowTok[128];
    __shared__ int sMeta[3];

    const int tid = threadIdx.x;
    if (tid == 0) tile_meta(blockIdx.x, sMeta);
    __syncthreads();
    const int e = sMeta[0];
    if (e < 0) return;
    const int rem = sMeta[2];
    const int n0 = blockIdx.y * 128;
    if (tid < 128) rowTok[tid] = (tid < rem) ? g_tok[sMeta[1] + tid] : g_tok[sMeta[1]];
    __syncthreads();

    const int lane = tid & 31, wid = tid >> 5;
    const int wm = wid >> 2, wn = wid & 3;
    const int mbase = wm * 64, nbase = wn * 32;
    const int lr = lane >> 2, lc = lane & 3;

    const uint32_t smemBase = smem_u32(dsm);

    // cp.async per-thread offsets (4 A + 4 B per chunk)
    const __half* aSrc[4];
    const __half* bSrc[4];
    uint32_t aDst[4], bDst[4];
#pragma unroll
    for (int i = 0; i < 4; i++) {
        int idx = tid + 256 * i;
        int m = idx >> 3, ch = idx & 7;
        aSrc[i] = g_xh + (size_t)rowTok[m] * DIM + ch * 8;
        aDst[i] = (uint32_t)(m * 128 + ((ch ^ (m & 7)) << 4));
        bSrc[i] = g_W1h + (size_t)e * HID * DIM + (size_t)(n0 + m) * DIM + ch * 8;
        bDst[i] = (uint32_t)(16384 + m * 128 + ((ch ^ (m & 7)) << 4));
    }
    // ldmatrix per-lane bases
    const int r7A = lane & 7, hiA = lane >> 4;
    const uint32_t aLdBase = (uint32_t)((mbase + (lane & 15)) * 128);
    const int r7B = lane & 7, hiB = (lane >> 3) & 1;
    const uint32_t bLdBase = (uint32_t)((nbase + (lane & 7)) * 128);

    float acc[4][4][4];
#pragma unroll
    for (int a = 0; a < 4; a++)
#pragma unroll
        for (int b = 0; b < 4; b++)
#pragma unroll
            for (int c = 0; c < 4; c++) acc[a][b][c] = 0.f;

    // 3-stage pipeline, NC = 4 chunks of K=64
    GEMM_LOAD(0, 0); CP_COMMIT();
    GEMM_LOAD(1, 1); CP_COMMIT();
#pragma unroll
    for (int c = 0; c < 4; c++) {
        CP_WAIT1();
        __syncthreads();
        if (c + 2 < 4) GEMM_LOAD((c + 2) % 3, c + 2);
        CP_COMMIT();
        GEMM_COMPUTE(c % 3);
    }

    // epilogue: acc -> Hs (reuse stage smem; half2, row stride 68 u32) -> coalesced STG
    __syncthreads();
    uint32_t* Hs = (uint32_t*)dsm;
    const float* bg = b1 + (size_t)e * HID + n0;
#pragma unroll
    for (int nt = 0; nt < 4; nt++) {
        int col = nbase + nt * 8 + lc * 2;
        float bb0 = __ldg(bg + col), bb1 = __ldg(bg + col + 1);
        int chn = col >> 1;
#pragma unroll
        for (int mt = 0; mt < 4; mt++) {
            int r0 = mbase + mt * 16 + lr;
            Hs[r0 * 68 + chn] = pk2h(fmaxf(acc[mt][nt][0] + bb0, 0.f),
                                     fmaxf(acc[mt][nt][1] + bb1, 0.f));
            Hs[(r0 + 8) * 68 + chn] = pk2h(fmaxf(acc[mt][nt][2] + bb0, 0.f),
                                           fmaxf(acc[mt][nt][3] + bb1, 0.f));
        }
    }
    __syncthreads();
    __half* hp = g_hidden + ((size_t)blockIdx.x * 128) * HID + n0;
#pragma unroll
    for (int j = 0; j < 8; j++) {
        int U = tid + 256 * j;
        int row = U >> 4, c4 = U & 15;
        uint4 v = *(const uint4*)&Hs[row * 68 + c4 * 4];
        *(uint4*)(hp + (size_t)row * HID + c4 * 8) = v;
    }
}

// ================ gemmB: out = (hidden @ W2 + b2) * gate ================
__global__ void __launch_bounds__(256, 2)
gemmB_kernel(const float* __restrict__ b2, float* __restrict__ out) {
    extern __shared__ __align__(16) char dsm[];
    __shared__ int rowTok[128];
    __shared__ float sGate[128];
    __shared__ int sMeta[3];

    const int tid = threadIdx.x;
    if (tid == 0) tile_meta(blockIdx.x, sMeta);
    __syncthreads();
    const int e = sMeta[0];
    if (e < 0) return;
    const int rem = sMeta[2];
    const int ybase = blockIdx.y * 128;
    if (tid < 128) {
        int tr = (tid < rem) ? g_tok[sMeta[1] + tid] : -1;
        rowTok[tid] = tr;
        sGate[tid] = (tr >= 0) ? g_gate[tr] : 0.f;
    }
    __syncthreads();

    const int lane = tid & 31, wid = tid >> 5;
    const int wm = wid >> 2, wn = wid & 3;
    const int mbase = wm * 64, nbase = wn * 32;
    const int lr = lane >> 2, lc = lane & 3;

    const uint32_t smemBase = smem_u32(dsm);

    const __half* aSrc[4];
    const __half* bSrc[4];
    uint32_t aDst[4], bDst[4];
#pragma unroll
    for (int i = 0; i < 4; i++) {
        int idx = tid + 256 * i;
        int m = idx >> 3, ch = idx & 7;
        aSrc[i] = g_hidden + ((size_t)blockIdx.x * 128 + m) * HID + ch * 8;
        aDst[i] = (uint32_t)(m * 128 + ((ch ^ (m & 7)) << 4));
        bSrc[i] = g_W2h + (size_t)e * DIM * HID + (size_t)(ybase + m) * HID + ch * 8;
        bDst[i] = (uint32_t)(16384 + m * 128 + ((ch ^ (m & 7)) << 4));
    }
    const int r7A = lane & 7, hiA = lane >> 4;
    const uint32_t aLdBase = (uint32_t)((mbase + (lane & 15)) * 128);
    const int r7B = lane & 7, hiB = (lane >> 3) & 1;
    const uint32_t bLdBase = (uint32_t)((nbase + (lane & 7)) * 128);

    float acc[4][4][4];
#pragma unroll
    for (int a = 0; a < 4; a++)
#pragma unroll
        for (int b = 0; b < 4; b++)
#pragma unroll
            for (int c = 0; c < 4; c++) acc[a][b][c] = 0.f;

    // 3-stage pipeline, NC = 16 chunks of K=64
    GEMM_LOAD(0, 0); CP_COMMIT();
    GEMM_LOAD(1, 1); CP_COMMIT();
    for (int c = 0; c < 16; c++) {
        CP_WAIT1();
        __syncthreads();
        if (c + 2 < 16) GEMM_LOAD((c + 2) % 3, c + 2);
        CP_COMMIT();
        GEMM_COMPUTE(c % 3);
    }

    // epilogue: bias + gate -> scattered out rows
    const float* bg = b2 + (size_t)e * DIM + ybase;
#pragma unroll
    for (int nt = 0; nt < 4; nt++) {
        int col = nbase + nt * 8 + lc * 2;
        float bb0 = __ldg(bg + col), bb1 = __ldg(bg + col + 1);
#pragma unroll
        for (int mt = 0; mt < 4; mt++) {
            int r0 = mbase + mt * 16 + lr;
            if (r0 < rem) {
                float g = sGate[r0];
                float2 o;
                o.x = (acc[mt][nt][0] + bb0) * g;
                o.y = (acc[mt][nt][1] + bb1) * g;
                *(float2*)&out[(size_t)rowTok[r0] * DIM + ybase + col] = o;
            }
            int r1 = r0 + 8;
            if (r1 < rem) {
                float g = sGate[r1];
                float2 o;
                o.x = (acc[mt][nt][2] + bb0) * g;
                o.y = (acc[mt][nt][3] + bb1) * g;
                *(float2*)&out[(size_t)rowTok[r1] * DIM + ybase + col] = o;
            }
        }
    }
}

// ---------------- launch ----------------
extern "C" void kernel_launch(void* const* d_in, const int* in_sizes, int n_in,
                              void* d_out, int out_size) {
    const float* x     = (const float*)d_in[0];
    const float* noise = (const float*)d_in[1];
    const float* Wr    = (const float*)d_in[2];
    const float* br    = (const float*)d_in[3];
    const float* Wa    = (const float*)d_in[4];
    const float* ba    = (const float*)d_in[5];
    const float* Wn    = (const float*)d_in[6];
    const float* bn    = (const float*)d_in[7];
    const float* W1    = (const float*)d_in[8];
    const float* b1    = (const float*)d_in[9];
    const float* W2    = (const float*)d_in[10];
    const float* b2    = (const float*)d_in[11];
    float* out = (float*)d_out;

    cudaFuncSetAttribute(gemmA_kernel, cudaFuncAttributeMaxDynamicSharedMemorySize, SMEM_GEMM);
    cudaFuncSetAttribute(gemmB_kernel, cudaFuncAttributeMaxDynamicSharedMemorySize, SMEM_GEMM);

    convX_kernel<<<NTOK * DIM / 4 / 256, 256>>>(x);
    convW1_kernel<<<dim3(HID / 32, DIM / 32, NE), dim3(32, 8)>>>(W1);
    convW2_kernel<<<dim3(DIM / 32, HID / 32, NE), dim3(32, 8)>>>(W2);
    avgpool_kernel<<<dim3(256, 16), 256>>>(x);
    prep_kernel<<<1, 128>>>(Wa, ba);
    router_kernel<<<256, 256>>>(x, noise, Wr, br, Wn, bn);
    scan_kernel<<<1, 1>>>();
    gemmA_kernel<<<dim3(MAXTILES, 8), 256, SMEM_GEMM>>>(b1);
    gemmB_kernel<<<dim3(MAXTILES, 2), 256, SMEM_GEMM>>>(b2, out);
}